// round 10
// baseline (speedup 1.0000x reference)
#include <cuda_runtime.h>
#include <math.h>
#include <stdint.h>

#define BN_EPS 1e-5f
#define BATCH 8192

// ---------------- scratch (device globals; no allocations allowed) ----------
__device__ float g_f[(size_t)BATCH * 64 * 8 * 8];     // flattened feat, tf32 (134MB)
__device__ float g_h1[(size_t)BATCH * 512];           // fc1 output, tf32 (16MB)
__device__ float g_wd1[(size_t)512 * 4096];           // tf32 wd1 (8MB)
__device__ float g_wd2t[(size_t)128 * 512];           // tf32 wd2
__device__ float g_wq[(size_t)9 * 64 * 36];           // conv2 W [q][oc][ic pad36] tf32
__device__ float g_w1q[(size_t)15 * 32 * 8];          // conv1 W [ic*5+ky][oc][kx pad8] tf32

__device__ __forceinline__ float to_tf32(float x) {
    uint32_t r;
    asm("cvt.rna.tf32.f32 %0, %1;" : "=r"(r) : "f"(x));
    return __uint_as_float(r);
}

__device__ __forceinline__ void mma_tf32(float* c, float2 a02, float2 a13, float2 b)
{
    asm volatile(
        "mma.sync.aligned.m16n8k8.row.col.f32.tf32.tf32.f32 "
        "{%0,%1,%2,%3}, {%4,%5,%6,%7}, {%8,%9}, {%0,%1,%2,%3};\n"
        : "+f"(c[0]), "+f"(c[1]), "+f"(c[2]), "+f"(c[3])
        : "r"(__float_as_uint(a02.x)), "r"(__float_as_uint(a13.x)),
          "r"(__float_as_uint(a02.y)), "r"(__float_as_uint(a13.y)),
          "r"(__float_as_uint(b.x)),   "r"(__float_as_uint(b.y)));
}

__device__ __forceinline__ void cp_async16(uint32_t dst_smem, const void* src) {
    asm volatile("cp.async.cg.shared.global [%0], [%1], 16;\n"
                 :: "r"(dst_smem), "l"(src));
}
__device__ __forceinline__ void cp_async8(uint32_t dst_smem, const void* src) {
    asm volatile("cp.async.ca.shared.global [%0], [%1], 8;\n"
                 :: "r"(dst_smem), "l"(src));
}
__device__ __forceinline__ void cp_commit() {
    asm volatile("cp.async.commit_group;\n" ::: "memory");
}
template<int N>
__device__ __forceinline__ void cp_wait() {
    asm volatile("cp.async.wait_group %0;\n" :: "n"(N) : "memory");
}

#define BARG(grp) asm volatile("bar.sync %0, 128;" :: "r"((grp) + 1) : "memory")

// ============================================================================
// Merged prep kernel: one launch does wd1, wd2, w2, w1 conversions.
// blocks [0,2048): wd1 f4 | [2048,2112): wd2 f4 | [2112,2184): w2 | [2184,2199): w1
// ============================================================================
__global__ __launch_bounds__(256) void cvt_all_kernel(
    const float* __restrict__ wd1, const float* __restrict__ wd2,
    const float* __restrict__ w2,  const float* __restrict__ w1)
{
    const int b = blockIdx.x, t = threadIdx.x;
    if (b < 2048) {
        int i = b * 256 + t;
        float4 v = ((const float4*)wd1)[i];
        v.x = to_tf32(v.x); v.y = to_tf32(v.y);
        v.z = to_tf32(v.z); v.w = to_tf32(v.w);
        ((float4*)g_wd1)[i] = v;
    } else if (b < 2112) {
        int i = (b - 2048) * 256 + t;
        float4 v = ((const float4*)wd2)[i];
        v.x = to_tf32(v.x); v.y = to_tf32(v.y);
        v.z = to_tf32(v.z); v.w = to_tf32(v.w);
        ((float4*)g_wd2t)[i] = v;
    } else if (b < 2184) {
        int i = (b - 2112) * 256 + t;       // 18432 = 64*32*9
        if (i < 18432) {
            int oc = i / 288;
            int rem = i % 288;
            int ic = rem / 9;
            int q  = rem % 9;
            g_wq[(q * 64 + oc) * 36 + ic] = to_tf32(w2[i]);
        }
    } else {
        int i = (b - 2184) * 256 + t;       // 3840 = 15*32*8
        if (i < 3840) {
            int tap = i >> 8;
            int oc  = (i >> 3) & 31;
            int kx  = i & 7;
            int ic  = tap / 5, ky = tap % 5;
            float v = (kx < 5) ? w1[oc * 75 + ic * 25 + ky * 5 + kx] : 0.f;
            g_w1q[i] = to_tf32(v);
        }
    }
}

// ============================================================================
// FUSED conv1+conv2 (proven R9 structure; attn now 2-way parallel).
// smem float layout (56752 floats = 227,008 B):
//   wq[20736] wb[3840] hwc[2][11664] xs[2][4104] attn[2][64] scr[2][128]
//   sc1[32] bi1[32] sc2[64] bi2[64] was[64]
// ============================================================================
#define FU_WQ     0
#define FU_WB     20736
#define FU_HWC    24576
#define FU_XS     47904
#define FU_ATTN   56112
#define FU_SCR    56240
#define FU_SC1    56496
#define FU_BI1    56528
#define FU_SC2    56560
#define FU_BI2    56624
#define FU_WAS    56688
#define FU_TOTAL  56752

__global__ __launch_bounds__(256) void conv_fused_kernel(
    const float* __restrict__ x,
    const float* __restrict__ b1, const float* __restrict__ g1,
    const float* __restrict__ be1, const float* __restrict__ m1,
    const float* __restrict__ v1,
    const float* __restrict__ b2, const float* __restrict__ g2,
    const float* __restrict__ be2, const float* __restrict__ m2,
    const float* __restrict__ v2, const float* __restrict__ wa,
    const float* __restrict__ ba)
{
    extern __shared__ float sm[];
    float* wq   = sm + FU_WQ;
    float* wb   = sm + FU_WB;
    float* sc1  = sm + FU_SC1;
    float* bi1  = sm + FU_BI1;
    float* sc2  = sm + FU_SC2;
    float* bi2  = sm + FU_BI2;
    float* was  = sm + FU_WAS;

    const int t = threadIdx.x;

    for (int i = t; i < 20736; i += 256) wq[i] = g_wq[i];
    for (int i = t; i < 3840; i += 256) wb[i] = g_w1q[i];
    for (int i = t; i < 23328; i += 256) sm[FU_HWC + i] = 0.f;
    for (int i = t; i < 8208; i += 256) sm[FU_XS + i] = 0.f;   // xs borders persist
    if (t < 32) {
        float s = g1[t] * rsqrtf(v1[t] + BN_EPS);
        sc1[t] = s;
        bi1[t] = be1[t] + (b1[t] - m1[t]) * s;
    }
    if (t < 64) {
        float s = g2[t] * rsqrtf(v2[t] + BN_EPS);
        sc2[t] = s;
        bi2[t] = be2[t] + (b2[t] - m2[t]) * s;
        was[t] = wa[t];
    }
    const float bav = ba[0];
    __syncthreads();

    const int grp  = t >> 7;
    const int u    = t & 127;
    const int w4   = u >> 5;
    const int lane = u & 31;
    const int g    = lane >> 2, tg = lane & 3;
    const int wm   = w4 >> 1, wn = w4 & 1;

    float* hwc  = sm + FU_HWC + grp * 11664;
    float* feat = hwc;                          // aliases hwc[0:4096)
    float* xs   = sm + FU_XS + grp * 4104;
    float* attn = sm + FU_ATTN + grp * 64;
    float* scr  = sm + FU_SCR + grp * 128;
    const uint32_t xsU = (uint32_t)__cvta_generic_to_shared(xs);

    int baseA[2][2];
#pragma unroll
    for (int mt = 0; mt < 2; mt++)
#pragma unroll
        for (int r = 0; r < 2; r++) {
            int m = wm * 32 + mt * 16 + g + 8 * r;
            baseA[mt][r] = 36 * (m >> 3) + 2 * (m & 7);
        }

    const int stride = gridDim.x * 2;
    const int n0 = blockIdx.x * 2 + grp;

    if (n0 < BATCH) {
        const float* src = x + (size_t)n0 * 3072;
#pragma unroll
        for (int j = 0; j < 12; j++) {
            int i2 = 2 * (u + 128 * j);
            int ic = i2 >> 10, rem = i2 & 1023, iy = rem >> 5, ix = rem & 31;
            cp_async8(xsU + (ic * 1368 + (iy + 2) * 38 + ix + 2) * 4, src + i2);
        }
        cp_commit();
    }

    for (int n = n0; n < BATCH; n += stride) {
        cp_wait<0>();
#pragma unroll
        for (int j = 0; j < 12; j++) {
            int i2 = 2 * (u + 128 * j);
            int ic = i2 >> 10, rem = i2 & 1023, iy = rem >> 5, ix = rem & 31;
            float2* p = (float2*)(xs + ic * 1368 + (iy + 2) * 38 + ix + 2);
            float2 v = *p;
            v.x = to_tf32(v.x); v.y = to_tf32(v.y);
            *p = v;
        }
        BARG(grp);

        // ---- conv1 mma ----
        {
            float acc[4][4][4];
#pragma unroll
            for (int mt = 0; mt < 4; mt++)
#pragma unroll
                for (int nt = 0; nt < 4; nt++)
#pragma unroll
                    for (int i = 0; i < 4; i++) acc[mt][nt][i] = 0.f;

#pragma unroll
            for (int tap = 0; tap < 15; tap++) {
                const int ic = tap / 5, ky = tap % 5;
                const float* Bp = wb + tap * 256 + g * 8 + 2 * tg;
                float2 bf[4];
#pragma unroll
                for (int nt = 0; nt < 4; nt++)
                    bf[nt] = *(const float2*)(Bp + nt * 64);
#pragma unroll
                for (int mt = 0; mt < 4; mt++) {
                    const int oy = (w4 << 2) + mt;
                    const float* Ap = xs + ic * 1368 + (2 * oy + ky) * 38 + 2 * tg;
                    float2 a0 = *(const float2*)(Ap + 2 * g);
                    float2 a1 = *(const float2*)(Ap + 2 * g + 16);
#pragma unroll
                    for (int nt = 0; nt < 4; nt++)
                        mma_tf32(acc[mt][nt], a0, a1, bf[nt]);
                }
            }
            BARG(grp);   // xs reads done -> safe to prefetch into xs

#pragma unroll
            for (int mt = 0; mt < 4; mt++) {
                const int oy = (w4 << 2) + mt;
#pragma unroll
                for (int nt = 0; nt < 4; nt++) {
                    const int oc = nt * 8 + 2 * tg;
                    const float s0 = sc1[oc], s1 = sc1[oc + 1];
                    const float t0 = bi1[oc], t1 = bi1[oc + 1];
                    float2 r0, r1;
                    r0.x = to_tf32(fmaxf(acc[mt][nt][0] * s0 + t0, 0.f));
                    r0.y = to_tf32(fmaxf(acc[mt][nt][1] * s1 + t1, 0.f));
                    r1.x = to_tf32(fmaxf(acc[mt][nt][2] * s0 + t0, 0.f));
                    r1.y = to_tf32(fmaxf(acc[mt][nt][3] * s1 + t1, 0.f));
                    *(float2*)&hwc[((oy + 1) * 18 + g + 1) * 36 + oc] = r0;
                    *(float2*)&hwc[((oy + 1) * 18 + g + 9) * 36 + oc] = r1;
                }
            }
            // re-zero border cells inside feat region [0, 4096)
            for (int jj = u; jj < 1044; jj += 128) {
                int j = jj / 36, ic = jj % 36;
                int pos;
                if (j < 18)      pos = j;
                else if (j < 28) { int r = j - 18; pos = (r / 2 + 1) * 18 + (r & 1) * 17; }
                else             pos = 108;
                hwc[pos * 36 + ic] = 0.f;
            }
            const int n_next = n + stride;
            if (n_next < BATCH) {
                const float* src = x + (size_t)n_next * 3072;
#pragma unroll
                for (int j = 0; j < 12; j++) {
                    int i2 = 2 * (u + 128 * j);
                    int ic = i2 >> 10, rem = i2 & 1023, iy = rem >> 5, ix = rem & 31;
                    cp_async8(xsU + (ic * 1368 + (iy + 2) * 38 + ix + 2) * 4, src + i2);
                }
                cp_commit();
            }
        }
        BARG(grp);   // hwc ready

        // ---- conv2 mma ----
        float acc[2][4][4];
#pragma unroll
        for (int mt = 0; mt < 2; mt++)
#pragma unroll
            for (int nt = 0; nt < 4; nt++)
#pragma unroll
                for (int i = 0; i < 4; i++) acc[mt][nt][i] = 0.f;

        for (int q = 0; q < 9; q++) {
            const int kh = q / 3, kw = q - kh * 3;
            const int dq = kh * 18 + kw;
            const float* A00 = hwc + (baseA[0][0] + dq) * 36 + 2 * tg;
            const float* A01 = hwc + (baseA[0][1] + dq) * 36 + 2 * tg;
            const float* A10 = hwc + (baseA[1][0] + dq) * 36 + 2 * tg;
            const float* A11 = hwc + (baseA[1][1] + dq) * 36 + 2 * tg;
            const float* Bq  = wq + (q * 64 + wn * 32 + g) * 36 + 2 * tg;
#pragma unroll
            for (int kk = 0; kk < 32; kk += 8) {
                float2 af[2][2], bf[4];
                af[0][0] = *(const float2*)(A00 + kk);
                af[0][1] = *(const float2*)(A01 + kk);
                af[1][0] = *(const float2*)(A10 + kk);
                af[1][1] = *(const float2*)(A11 + kk);
#pragma unroll
                for (int nt = 0; nt < 4; nt++)
                    bf[nt] = *(const float2*)(Bq + nt * (8 * 36) + kk);
#pragma unroll
                for (int mt = 0; mt < 2; mt++)
#pragma unroll
                    for (int nt = 0; nt < 4; nt++)
                        mma_tf32(acc[mt][nt], af[mt][0], af[mt][1], bf[nt]);
            }
        }
        BARG(grp);   // hwc reads done (incl. feat region)

        // BN + ReLU -> feat[oc][pos]
#pragma unroll
        for (int mt = 0; mt < 2; mt++) {
            const int m0 = wm * 32 + mt * 16 + g;
#pragma unroll
            for (int nt = 0; nt < 4; nt++) {
                const int c0 = wn * 32 + nt * 8 + 2 * tg;
                float s0 = sc2[c0], s1 = sc2[c0 + 1];
                float t0 = bi2[c0], t1 = bi2[c0 + 1];
                feat[c0 * 64 + m0]           = fmaxf(acc[mt][nt][0] * s0 + t0, 0.f);
                feat[(c0 + 1) * 64 + m0]     = fmaxf(acc[mt][nt][1] * s1 + t1, 0.f);
                feat[c0 * 64 + m0 + 8]       = fmaxf(acc[mt][nt][2] * s0 + t0, 0.f);
                feat[(c0 + 1) * 64 + m0 + 8] = fmaxf(acc[mt][nt][3] * s1 + t1, 0.f);
            }
        }
        BARG(grp);

        // Haar cD * upsample
        for (int qq = u; qq < 1024; qq += 128) {
            int c = qq >> 4, blk = qq & 15;
            int bI = blk >> 2, bJ = blk & 3;
            int p00 = c * 64 + (bI * 2) * 8 + bJ * 2;
            float a = feat[p00], b = feat[p00 + 1];
            float cc = feat[p00 + 8], d = feat[p00 + 9];
            float v = (a - b - cc + d) * 0.5f;
            feat[p00]     = a  * v;
            feat[p00 + 1] = b  * v;
            feat[p00 + 8] = cc * v;
            feat[p00 + 9] = d  * v;
        }
        BARG(grp);

        // 1x1 attn: two 32-channel partial sums per output (all 128 threads)
        {
            const int half = u >> 6, uu = u & 63;
            float s = (half == 0) ? bav : 0.f;
            const int cb = half * 32;
#pragma unroll 8
            for (int c = 0; c < 32; c++)
                s += feat[(cb + c) * 64 + uu] * was[cb + c];
            scr[half * 64 + uu] = s;
        }
        BARG(grp);
        if (u < 64) {
            float s = scr[u] + scr[64 + u];
            attn[u] = 1.f / (1.f + __expf(-s));
        }
        BARG(grp);

        // multiply & store tf32
        float* fg = g_f + (size_t)n * 4096;
        for (int i = u; i < 4096; i += 128)
            fg[i] = to_tf32(feat[i] * attn[i & 63]);
        BARG(grp);   // feat reads done; next iter may overwrite hwc
    }
}

// ============================================================================
// tf32 GEMM v4: 128x128 tile, 256 threads (8 warps, warp tile 32x64),
// cp.async 4-stage, distance-3 prefetch, ONE barrier per k16.
// Smem row stride 20: 20g mod 32 all-distinct for g=0..7 -> fragment LDS
// conflict-free (stride 24 had 2-way g/g+4 conflicts).
// MODE 0: g_h1 = tf32(relu(g_f @ g_wd1^T + bias)),   ldc=512
// MODE 1: out  = sigmoid(g_h1 @ g_wd2t^T + bias),    ldc=128
// ============================================================================
#define GSTAGE 4
#define GSTRIDE 2560            // 128 rows * 20 floats per stage

template<int KDIM, int MODE>
__global__ __launch_bounds__(256, 2) void gemm_tf32_kernel(
    const float* __restrict__ bias, float* __restrict__ Cout)
{
    const float* A = (MODE == 0) ? g_f  : g_h1;
    const float* B = (MODE == 0) ? g_wd1 : g_wd2t;
    float*       C = (MODE == 0) ? g_h1 : Cout;
    const int  ldc = (MODE == 0) ? 512  : 128;

    extern __shared__ float smx[];
    float* As = smx;                        // [4][2560]
    float* Bs = smx + GSTAGE * GSTRIDE;     // [4][2560]
    const uint32_t AsU = (uint32_t)__cvta_generic_to_shared(As);
    const uint32_t BsU = (uint32_t)__cvta_generic_to_shared(Bs);

    const int t  = threadIdx.x;
    const int bn = blockIdx.x, bm = blockIdx.y;
    const int w  = t >> 5, lane = t & 31;
    const int wm = w >> 1, wn = w & 1;      // 4 x 2 warp grid, warp tile 32x64
    const int g  = lane >> 2, tg = lane & 3;

    int rowv[2], kov[2];
#pragma unroll
    for (int j = 0; j < 2; j++) {
        int v = t + 256 * j;
        rowv[j] = v >> 2;
        kov[j]  = (v & 3) * 4;
    }
    const float* PA[2];
    const float* PB[2];
    uint32_t DA[2], DB[2];
#pragma unroll
    for (int j = 0; j < 2; j++) {
        PA[j] = A + (size_t)(bm * 128 + rowv[j]) * KDIM + kov[j];
        PB[j] = B + (size_t)(bn * 128 + rowv[j]) * KDIM + kov[j];
        DA[j] = AsU + (rowv[j] * 20 + kov[j]) * 4;
        DB[j] = BsU + (rowv[j] * 20 + kov[j]) * 4;
    }

    const int NIT = KDIM / 16;

#pragma unroll
    for (int s = 0; s < 3; s++) {
#pragma unroll
        for (int j = 0; j < 2; j++) {
            cp_async16(DA[j] + s * (GSTRIDE * 4), PA[j] + s * 16);
            cp_async16(DB[j] + s * (GSTRIDE * 4), PB[j] + s * 16);
        }
        cp_commit();
    }

    float acc[2][8][4];
#pragma unroll
    for (int mt = 0; mt < 2; mt++)
#pragma unroll
        for (int nt = 0; nt < 8; nt++)
#pragma unroll
            for (int i = 0; i < 4; i++) acc[mt][nt][i] = 0.f;

    const int ar0 = (wm * 32 + g) * 20 + 2 * tg;       // +mt*320, +160 row+8
    const int br0 = (wn * 64 + g) * 20 + 2 * tg;       // +nt*160

#pragma unroll 1
    for (int it = 0; it < NIT; it++) {
        if (it < NIT - 2)       cp_wait<2>();
        else if (it == NIT - 2) cp_wait<1>();
        else                    cp_wait<0>();
        __syncthreads();

        if (it + 3 < NIT) {
            const int sn = (it + 3) & 3;
#pragma unroll
            for (int j = 0; j < 2; j++) {
                cp_async16(DA[j] + sn * (GSTRIDE * 4), PA[j] + (it + 3) * 16);
                cp_async16(DB[j] + sn * (GSTRIDE * 4), PB[j] + (it + 3) * 16);
            }
            cp_commit();
        }

        const int s = it & 3;
        const float* Ab = As + s * GSTRIDE;
        const float* Bb = Bs + s * GSTRIDE;
#pragma unroll
        for (int kk = 0; kk < 16; kk += 8) {
            float2 af[2][2], bf[8];
#pragma unroll
            for (int mt = 0; mt < 2; mt++) {
                af[mt][0] = *(const float2*)&Ab[ar0 + mt * 320 + kk];
                af[mt][1] = *(const float2*)&Ab[ar0 + mt * 320 + 160 + kk];
            }
#pragma unroll
            for (int nt = 0; nt < 8; nt++)
                bf[nt] = *(const float2*)&Bb[br0 + nt * 160 + kk];
#pragma unroll
            for (int mt = 0; mt < 2; mt++)
#pragma unroll
                for (int nt = 0; nt < 8; nt++)
                    mma_tf32(acc[mt][nt], af[mt][0], af[mt][1], bf[nt]);
        }
    }

#pragma unroll
    for (int mt = 0; mt < 2; mt++) {
        const int m0 = bm * 128 + wm * 32 + mt * 16 + g;
#pragma unroll
        for (int nt = 0; nt < 8; nt++) {
            const int n0 = bn * 128 + wn * 64 + nt * 8 + 2 * tg;
            const float b0 = bias[n0], b1 = bias[n0 + 1];
            float2 r0, r1;
            if (MODE == 0) {
                r0.x = to_tf32(fmaxf(acc[mt][nt][0] + b0, 0.f));
                r0.y = to_tf32(fmaxf(acc[mt][nt][1] + b1, 0.f));
                r1.x = to_tf32(fmaxf(acc[mt][nt][2] + b0, 0.f));
                r1.y = to_tf32(fmaxf(acc[mt][nt][3] + b1, 0.f));
            } else {
                r0.x = 1.f / (1.f + __expf(-(acc[mt][nt][0] + b0)));
                r0.y = 1.f / (1.f + __expf(-(acc[mt][nt][1] + b1)));
                r1.x = 1.f / (1.f + __expf(-(acc[mt][nt][2] + b0)));
                r1.y = 1.f / (1.f + __expf(-(acc[mt][nt][3] + b1)));
            }
            *(float2*)&C[(size_t)m0 * ldc + n0]       = r0;
            *(float2*)&C[(size_t)(m0 + 8) * ldc + n0] = r1;
        }
    }
}

// ============================================================================
extern "C" void kernel_launch(void* const* d_in, const int* in_sizes, int n_in,
                              void* d_out, int out_size)
{
    const float* x   = (const float*)d_in[0];
    const float* w1  = (const float*)d_in[1];
    const float* b1  = (const float*)d_in[2];
    const float* g1  = (const float*)d_in[3];
    const float* be1 = (const float*)d_in[4];
    const float* m1  = (const float*)d_in[5];
    const float* v1  = (const float*)d_in[6];
    const float* w2  = (const float*)d_in[7];
    const float* b2  = (const float*)d_in[8];
    const float* g2  = (const float*)d_in[9];
    const float* be2 = (const float*)d_in[10];
    const float* m2  = (const float*)d_in[11];
    const float* v2  = (const float*)d_in[12];
    const float* wa  = (const float*)d_in[13];
    const float* ba  = (const float*)d_in[14];
    const float* wd1 = (const float*)d_in[15];
    const float* bd1 = (const float*)d_in[16];
    const float* wd2 = (const float*)d_in[17];
    const float* bd2 = (const float*)d_in[18];
    float* out = (float*)d_out;

    const int fused_smem = FU_TOTAL * 4;                    // 227,008 B
    const int gemm_smem  = GSTAGE * GSTRIDE * 2 * 4;        // 81,920 B
    cudaFuncSetAttribute(conv_fused_kernel,
                         cudaFuncAttributeMaxDynamicSharedMemorySize, fused_smem);
    cudaFuncSetAttribute(gemm_tf32_kernel<4096, 0>,
                         cudaFuncAttributeMaxDynamicSharedMemorySize, gemm_smem);
    cudaFuncSetAttribute(gemm_tf32_kernel<512, 1>,
                         cudaFuncAttributeMaxDynamicSharedMemorySize, gemm_smem);

    cvt_all_kernel<<<2199, 256>>>(wd1, wd2, w2, w1);

    conv_fused_kernel<<<148, 256, fused_smem>>>(x, b1, g1, be1, m1, v1,
                                                b2, g2, be2, m2, v2, wa, ba);

    dim3 grid_fc1(4, 64);
    gemm_tf32_kernel<4096, 0><<<grid_fc1, 256, gemm_smem>>>(bd1, out);
    dim3 grid_fc2(1, 64);
    gemm_tf32_kernel<512, 1><<<grid_fc2, 256, gemm_smem>>>(bd2, out);
}

// round 11
// speedup vs baseline: 1.1071x; 1.1071x over previous
#include <cuda_runtime.h>
#include <math.h>
#include <stdint.h>

#define BN_EPS 1e-5f
#define BATCH 8192

// ---------------- scratch (device globals; no allocations allowed) ----------
__device__ float g_f[(size_t)BATCH * 64 * 8 * 8];     // flattened feat, tf32 (134MB)
__device__ float g_h1[(size_t)BATCH * 512];           // fc1 output, tf32 (16MB)
__device__ float g_wd1[(size_t)512 * 4096];           // tf32 wd1 (8MB)
__device__ float g_wd2t[(size_t)128 * 512];           // tf32 wd2
__device__ float g_wq[(size_t)9 * 64 * 36];           // conv2 W [q][oc][ic pad36] tf32
__device__ float g_w1q[(size_t)15 * 32 * 8];          // conv1 W [ic*5+ky][oc][kx pad8] tf32

__device__ __forceinline__ float to_tf32(float x) {
    uint32_t r;
    asm("cvt.rna.tf32.f32 %0, %1;" : "=r"(r) : "f"(x));
    return __uint_as_float(r);
}

__device__ __forceinline__ void mma_tf32(float* c, float2 a02, float2 a13, float2 b)
{
    asm volatile(
        "mma.sync.aligned.m16n8k8.row.col.f32.tf32.tf32.f32 "
        "{%0,%1,%2,%3}, {%4,%5,%6,%7}, {%8,%9}, {%0,%1,%2,%3};\n"
        : "+f"(c[0]), "+f"(c[1]), "+f"(c[2]), "+f"(c[3])
        : "r"(__float_as_uint(a02.x)), "r"(__float_as_uint(a13.x)),
          "r"(__float_as_uint(a02.y)), "r"(__float_as_uint(a13.y)),
          "r"(__float_as_uint(b.x)),   "r"(__float_as_uint(b.y)));
}

__device__ __forceinline__ void cp_async16(uint32_t dst_smem, const void* src) {
    asm volatile("cp.async.cg.shared.global [%0], [%1], 16;\n"
                 :: "r"(dst_smem), "l"(src));
}
__device__ __forceinline__ void cp_async8(uint32_t dst_smem, const void* src) {
    asm volatile("cp.async.ca.shared.global [%0], [%1], 8;\n"
                 :: "r"(dst_smem), "l"(src));
}
__device__ __forceinline__ void cp_commit() {
    asm volatile("cp.async.commit_group;\n" ::: "memory");
}
template<int N>
__device__ __forceinline__ void cp_wait() {
    asm volatile("cp.async.wait_group %0;\n" :: "n"(N) : "memory");
}

#define BARG(grp) asm volatile("bar.sync %0, 128;" :: "r"((grp) + 1) : "memory")

// ============================================================================
// Merged prep kernel: one launch does wd1, wd2, w2, w1 conversions.
// blocks [0,2048): wd1 f4 | [2048,2112): wd2 f4 | [2112,2184): w2 | [2184,2199): w1
// ============================================================================
__global__ __launch_bounds__(256) void cvt_all_kernel(
    const float* __restrict__ wd1, const float* __restrict__ wd2,
    const float* __restrict__ w2,  const float* __restrict__ w1)
{
    const int b = blockIdx.x, t = threadIdx.x;
    if (b < 2048) {
        int i = b * 256 + t;
        float4 v = ((const float4*)wd1)[i];
        v.x = to_tf32(v.x); v.y = to_tf32(v.y);
        v.z = to_tf32(v.z); v.w = to_tf32(v.w);
        ((float4*)g_wd1)[i] = v;
    } else if (b < 2112) {
        int i = (b - 2048) * 256 + t;
        float4 v = ((const float4*)wd2)[i];
        v.x = to_tf32(v.x); v.y = to_tf32(v.y);
        v.z = to_tf32(v.z); v.w = to_tf32(v.w);
        ((float4*)g_wd2t)[i] = v;
    } else if (b < 2184) {
        int i = (b - 2112) * 256 + t;       // 18432 = 64*32*9
        if (i < 18432) {
            int oc = i / 288;
            int rem = i % 288;
            int ic = rem / 9;
            int q  = rem % 9;
            g_wq[(q * 64 + oc) * 36 + ic] = to_tf32(w2[i]);
        }
    } else {
        int i = (b - 2184) * 256 + t;       // 3840 = 15*32*8
        if (i < 3840) {
            int tap = i >> 8;
            int oc  = (i >> 3) & 31;
            int kx  = i & 7;
            int ic  = tap / 5, ky = tap % 5;
            float v = (kx < 5) ? w1[oc * 75 + ic * 25 + ky * 5 + kx] : 0.f;
            g_w1q[i] = to_tf32(v);
        }
    }
}

// ============================================================================
// FUSED conv1+conv2 (proven structure; attn 2-way parallel).
// smem float layout (56752 floats = 227,008 B):
//   wq[20736] wb[3840] hwc[2][11664] xs[2][4104] attn[2][64] scr[2][128]
//   sc1[32] bi1[32] sc2[64] bi2[64] was[64]
// ============================================================================
#define FU_WQ     0
#define FU_WB     20736
#define FU_HWC    24576
#define FU_XS     47904
#define FU_ATTN   56112
#define FU_SCR    56240
#define FU_SC1    56496
#define FU_BI1    56528
#define FU_SC2    56560
#define FU_BI2    56624
#define FU_WAS    56688
#define FU_TOTAL  56752

__global__ __launch_bounds__(256) void conv_fused_kernel(
    const float* __restrict__ x,
    const float* __restrict__ b1, const float* __restrict__ g1,
    const float* __restrict__ be1, const float* __restrict__ m1,
    const float* __restrict__ v1,
    const float* __restrict__ b2, const float* __restrict__ g2,
    const float* __restrict__ be2, const float* __restrict__ m2,
    const float* __restrict__ v2, const float* __restrict__ wa,
    const float* __restrict__ ba)
{
    extern __shared__ float sm[];
    float* wq   = sm + FU_WQ;
    float* wb   = sm + FU_WB;
    float* sc1  = sm + FU_SC1;
    float* bi1  = sm + FU_BI1;
    float* sc2  = sm + FU_SC2;
    float* bi2  = sm + FU_BI2;
    float* was  = sm + FU_WAS;

    const int t = threadIdx.x;

    for (int i = t; i < 20736; i += 256) wq[i] = g_wq[i];
    for (int i = t; i < 3840; i += 256) wb[i] = g_w1q[i];
    for (int i = t; i < 23328; i += 256) sm[FU_HWC + i] = 0.f;
    for (int i = t; i < 8208; i += 256) sm[FU_XS + i] = 0.f;   // xs borders persist
    if (t < 32) {
        float s = g1[t] * rsqrtf(v1[t] + BN_EPS);
        sc1[t] = s;
        bi1[t] = be1[t] + (b1[t] - m1[t]) * s;
    }
    if (t < 64) {
        float s = g2[t] * rsqrtf(v2[t] + BN_EPS);
        sc2[t] = s;
        bi2[t] = be2[t] + (b2[t] - m2[t]) * s;
        was[t] = wa[t];
    }
    const float bav = ba[0];
    __syncthreads();

    const int grp  = t >> 7;
    const int u    = t & 127;
    const int w4   = u >> 5;
    const int lane = u & 31;
    const int g    = lane >> 2, tg = lane & 3;
    const int wm   = w4 >> 1, wn = w4 & 1;

    float* hwc  = sm + FU_HWC + grp * 11664;
    float* feat = hwc;                          // aliases hwc[0:4096)
    float* xs   = sm + FU_XS + grp * 4104;
    float* attn = sm + FU_ATTN + grp * 64;
    float* scr  = sm + FU_SCR + grp * 128;
    const uint32_t xsU = (uint32_t)__cvta_generic_to_shared(xs);

    int baseA[2][2];
#pragma unroll
    for (int mt = 0; mt < 2; mt++)
#pragma unroll
        for (int r = 0; r < 2; r++) {
            int m = wm * 32 + mt * 16 + g + 8 * r;
            baseA[mt][r] = 36 * (m >> 3) + 2 * (m & 7);
        }

    const int stride = gridDim.x * 2;
    const int n0 = blockIdx.x * 2 + grp;

    if (n0 < BATCH) {
        const float* src = x + (size_t)n0 * 3072;
#pragma unroll
        for (int j = 0; j < 12; j++) {
            int i2 = 2 * (u + 128 * j);
            int ic = i2 >> 10, rem = i2 & 1023, iy = rem >> 5, ix = rem & 31;
            cp_async8(xsU + (ic * 1368 + (iy + 2) * 38 + ix + 2) * 4, src + i2);
        }
        cp_commit();
    }

    for (int n = n0; n < BATCH; n += stride) {
        cp_wait<0>();
#pragma unroll
        for (int j = 0; j < 12; j++) {
            int i2 = 2 * (u + 128 * j);
            int ic = i2 >> 10, rem = i2 & 1023, iy = rem >> 5, ix = rem & 31;
            float2* p = (float2*)(xs + ic * 1368 + (iy + 2) * 38 + ix + 2);
            float2 v = *p;
            v.x = to_tf32(v.x); v.y = to_tf32(v.y);
            *p = v;
        }
        BARG(grp);

        // ---- conv1 mma ----
        {
            float acc[4][4][4];
#pragma unroll
            for (int mt = 0; mt < 4; mt++)
#pragma unroll
                for (int nt = 0; nt < 4; nt++)
#pragma unroll
                    for (int i = 0; i < 4; i++) acc[mt][nt][i] = 0.f;

#pragma unroll
            for (int tap = 0; tap < 15; tap++) {
                const int ic = tap / 5, ky = tap % 5;
                const float* Bp = wb + tap * 256 + g * 8 + 2 * tg;
                float2 bf[4];
#pragma unroll
                for (int nt = 0; nt < 4; nt++)
                    bf[nt] = *(const float2*)(Bp + nt * 64);
#pragma unroll
                for (int mt = 0; mt < 4; mt++) {
                    const int oy = (w4 << 2) + mt;
                    const float* Ap = xs + ic * 1368 + (2 * oy + ky) * 38 + 2 * tg;
                    float2 a0 = *(const float2*)(Ap + 2 * g);
                    float2 a1 = *(const float2*)(Ap + 2 * g + 16);
#pragma unroll
                    for (int nt = 0; nt < 4; nt++)
                        mma_tf32(acc[mt][nt], a0, a1, bf[nt]);
                }
            }
            BARG(grp);   // xs reads done -> safe to prefetch into xs

#pragma unroll
            for (int mt = 0; mt < 4; mt++) {
                const int oy = (w4 << 2) + mt;
#pragma unroll
                for (int nt = 0; nt < 4; nt++) {
                    const int oc = nt * 8 + 2 * tg;
                    const float s0 = sc1[oc], s1 = sc1[oc + 1];
                    const float t0 = bi1[oc], t1 = bi1[oc + 1];
                    float2 r0, r1;
                    r0.x = to_tf32(fmaxf(acc[mt][nt][0] * s0 + t0, 0.f));
                    r0.y = to_tf32(fmaxf(acc[mt][nt][1] * s1 + t1, 0.f));
                    r1.x = to_tf32(fmaxf(acc[mt][nt][2] * s0 + t0, 0.f));
                    r1.y = to_tf32(fmaxf(acc[mt][nt][3] * s1 + t1, 0.f));
                    *(float2*)&hwc[((oy + 1) * 18 + g + 1) * 36 + oc] = r0;
                    *(float2*)&hwc[((oy + 1) * 18 + g + 9) * 36 + oc] = r1;
                }
            }
            // re-zero border cells inside feat region [0, 4096)
            for (int jj = u; jj < 1044; jj += 128) {
                int j = jj / 36, ic = jj % 36;
                int pos;
                if (j < 18)      pos = j;
                else if (j < 28) { int r = j - 18; pos = (r / 2 + 1) * 18 + (r & 1) * 17; }
                else             pos = 108;
                hwc[pos * 36 + ic] = 0.f;
            }
            const int n_next = n + stride;
            if (n_next < BATCH) {
                const float* src = x + (size_t)n_next * 3072;
#pragma unroll
                for (int j = 0; j < 12; j++) {
                    int i2 = 2 * (u + 128 * j);
                    int ic = i2 >> 10, rem = i2 & 1023, iy = rem >> 5, ix = rem & 31;
                    cp_async8(xsU + (ic * 1368 + (iy + 2) * 38 + ix + 2) * 4, src + i2);
                }
                cp_commit();
            }
        }
        BARG(grp);   // hwc ready

        // ---- conv2 mma ----
        float acc[2][4][4];
#pragma unroll
        for (int mt = 0; mt < 2; mt++)
#pragma unroll
            for (int nt = 0; nt < 4; nt++)
#pragma unroll
                for (int i = 0; i < 4; i++) acc[mt][nt][i] = 0.f;

        for (int q = 0; q < 9; q++) {
            const int kh = q / 3, kw = q - kh * 3;
            const int dq = kh * 18 + kw;
            const float* A00 = hwc + (baseA[0][0] + dq) * 36 + 2 * tg;
            const float* A01 = hwc + (baseA[0][1] + dq) * 36 + 2 * tg;
            const float* A10 = hwc + (baseA[1][0] + dq) * 36 + 2 * tg;
            const float* A11 = hwc + (baseA[1][1] + dq) * 36 + 2 * tg;
            const float* Bq  = wq + (q * 64 + wn * 32 + g) * 36 + 2 * tg;
#pragma unroll
            for (int kk = 0; kk < 32; kk += 8) {
                float2 af[2][2], bf[4];
                af[0][0] = *(const float2*)(A00 + kk);
                af[0][1] = *(const float2*)(A01 + kk);
                af[1][0] = *(const float2*)(A10 + kk);
                af[1][1] = *(const float2*)(A11 + kk);
#pragma unroll
                for (int nt = 0; nt < 4; nt++)
                    bf[nt] = *(const float2*)(Bq + nt * (8 * 36) + kk);
#pragma unroll
                for (int mt = 0; mt < 2; mt++)
#pragma unroll
                    for (int nt = 0; nt < 4; nt++)
                        mma_tf32(acc[mt][nt], af[mt][0], af[mt][1], bf[nt]);
            }
        }
        BARG(grp);   // hwc reads done (incl. feat region)

        // BN + ReLU -> feat[oc][pos]
#pragma unroll
        for (int mt = 0; mt < 2; mt++) {
            const int m0 = wm * 32 + mt * 16 + g;
#pragma unroll
            for (int nt = 0; nt < 4; nt++) {
                const int c0 = wn * 32 + nt * 8 + 2 * tg;
                float s0 = sc2[c0], s1 = sc2[c0 + 1];
                float t0 = bi2[c0], t1 = bi2[c0 + 1];
                feat[c0 * 64 + m0]           = fmaxf(acc[mt][nt][0] * s0 + t0, 0.f);
                feat[(c0 + 1) * 64 + m0]     = fmaxf(acc[mt][nt][1] * s1 + t1, 0.f);
                feat[c0 * 64 + m0 + 8]       = fmaxf(acc[mt][nt][2] * s0 + t0, 0.f);
                feat[(c0 + 1) * 64 + m0 + 8] = fmaxf(acc[mt][nt][3] * s1 + t1, 0.f);
            }
        }
        BARG(grp);

        // Haar cD * upsample
        for (int qq = u; qq < 1024; qq += 128) {
            int c = qq >> 4, blk = qq & 15;
            int bI = blk >> 2, bJ = blk & 3;
            int p00 = c * 64 + (bI * 2) * 8 + bJ * 2;
            float a = feat[p00], b = feat[p00 + 1];
            float cc = feat[p00 + 8], d = feat[p00 + 9];
            float v = (a - b - cc + d) * 0.5f;
            feat[p00]     = a  * v;
            feat[p00 + 1] = b  * v;
            feat[p00 + 8] = cc * v;
            feat[p00 + 9] = d  * v;
        }
        BARG(grp);

        // 1x1 attn: two 32-channel partial sums per output
        {
            const int half = u >> 6, uu = u & 63;
            float s = (half == 0) ? bav : 0.f;
            const int cb = half * 32;
#pragma unroll 8
            for (int c = 0; c < 32; c++)
                s += feat[(cb + c) * 64 + uu] * was[cb + c];
            scr[half * 64 + uu] = s;
        }
        BARG(grp);
        if (u < 64) {
            float s = scr[u] + scr[64 + u];
            attn[u] = 1.f / (1.f + __expf(-s));
        }
        BARG(grp);

        // multiply & store tf32
        float* fg = g_f + (size_t)n * 4096;
        for (int i = u; i < 4096; i += 128)
            fg[i] = to_tf32(feat[i] * attn[i & 63]);
        BARG(grp);   // feat reads done; next iter may overwrite hwc
    }
}

// ============================================================================
// tf32 GEMM (PROVEN R9): 128x128 tile, 256 threads (8 warps, warp tile 32x64),
// cp.async 4-stage, distance-3 prefetch, ONE barrier per k16.
// Smem row stride 24 — conflict-free for LDS.64 (half-warp phase analysis:
// g=0..3 banks {0-6, 24-30, 16-22, 8-14} = all 32 distinct).
// MODE 0: g_h1 = tf32(relu(g_f @ g_wd1^T + bias)),   ldc=512
// MODE 1: out  = sigmoid(g_h1 @ g_wd2t^T + bias),    ldc=128
// ============================================================================
#define GSTAGE 4
#define GSTRIDE 3072            // 128 rows * 24 floats per stage

template<int KDIM, int MODE>
__global__ __launch_bounds__(256, 2) void gemm_tf32_kernel(
    const float* __restrict__ bias, float* __restrict__ Cout)
{
    const float* A = (MODE == 0) ? g_f  : g_h1;
    const float* B = (MODE == 0) ? g_wd1 : g_wd2t;
    float*       C = (MODE == 0) ? g_h1 : Cout;
    const int  ldc = (MODE == 0) ? 512  : 128;

    extern __shared__ float smx[];
    float* As = smx;                        // [4][3072]
    float* Bs = smx + GSTAGE * GSTRIDE;     // [4][3072]
    const uint32_t AsU = (uint32_t)__cvta_generic_to_shared(As);
    const uint32_t BsU = (uint32_t)__cvta_generic_to_shared(Bs);

    const int t  = threadIdx.x;
    const int bn = blockIdx.x, bm = blockIdx.y;
    const int w  = t >> 5, lane = t & 31;
    const int wm = w >> 1, wn = w & 1;      // 4 x 2 warp grid, warp tile 32x64
    const int g  = lane >> 2, tg = lane & 3;

    int rowv[2], kov[2];
#pragma unroll
    for (int j = 0; j < 2; j++) {
        int v = t + 256 * j;
        rowv[j] = v >> 2;
        kov[j]  = (v & 3) * 4;
    }
    const float* PA[2];
    const float* PB[2];
    uint32_t DA[2], DB[2];
#pragma unroll
    for (int j = 0; j < 2; j++) {
        PA[j] = A + (size_t)(bm * 128 + rowv[j]) * KDIM + kov[j];
        PB[j] = B + (size_t)(bn * 128 + rowv[j]) * KDIM + kov[j];
        DA[j] = AsU + (rowv[j] * 24 + kov[j]) * 4;
        DB[j] = BsU + (rowv[j] * 24 + kov[j]) * 4;
    }

    const int NIT = KDIM / 16;

#pragma unroll
    for (int s = 0; s < 3; s++) {
#pragma unroll
        for (int j = 0; j < 2; j++) {
            cp_async16(DA[j] + s * (GSTRIDE * 4), PA[j] + s * 16);
            cp_async16(DB[j] + s * (GSTRIDE * 4), PB[j] + s * 16);
        }
        cp_commit();
    }

    float acc[2][8][4];
#pragma unroll
    for (int mt = 0; mt < 2; mt++)
#pragma unroll
        for (int nt = 0; nt < 8; nt++)
#pragma unroll
            for (int i = 0; i < 4; i++) acc[mt][nt][i] = 0.f;

    const int ar0 = (wm * 32 + g) * 24 + 2 * tg;       // +mt*384, +192 row+8
    const int br0 = (wn * 64 + g) * 24 + 2 * tg;       // +nt*192

#pragma unroll 1
    for (int it = 0; it < NIT; it++) {
        if (it < NIT - 2)       cp_wait<2>();
        else if (it == NIT - 2) cp_wait<1>();
        else                    cp_wait<0>();
        __syncthreads();

        if (it + 3 < NIT) {
            const int sn = (it + 3) & 3;
#pragma unroll
            for (int j = 0; j < 2; j++) {
                cp_async16(DA[j] + sn * (GSTRIDE * 4), PA[j] + (it + 3) * 16);
                cp_async16(DB[j] + sn * (GSTRIDE * 4), PB[j] + (it + 3) * 16);
            }
            cp_commit();
        }

        const int s = it & 3;
        const float* Ab = As + s * GSTRIDE;
        const float* Bb = Bs + s * GSTRIDE;
#pragma unroll
        for (int kk = 0; kk < 16; kk += 8) {
            float2 af[2][2], bf[8];
#pragma unroll
            for (int mt = 0; mt < 2; mt++) {
                af[mt][0] = *(const float2*)&Ab[ar0 + mt * 384 + kk];
                af[mt][1] = *(const float2*)&Ab[ar0 + mt * 384 + 192 + kk];
            }
#pragma unroll
            for (int nt = 0; nt < 8; nt++)
                bf[nt] = *(const float2*)&Bb[br0 + nt * 192 + kk];
#pragma unroll
            for (int mt = 0; mt < 2; mt++)
#pragma unroll
                for (int nt = 0; nt < 8; nt++)
                    mma_tf32(acc[mt][nt], af[mt][0], af[mt][1], bf[nt]);
        }
    }

#pragma unroll
    for (int mt = 0; mt < 2; mt++) {
        const int m0 = bm * 128 + wm * 32 + mt * 16 + g;
#pragma unroll
        for (int nt = 0; nt < 8; nt++) {
            const int n0 = bn * 128 + wn * 64 + nt * 8 + 2 * tg;
            const float b0 = bias[n0], b1 = bias[n0 + 1];
            float2 r0, r1;
            if (MODE == 0) {
                r0.x = to_tf32(fmaxf(acc[mt][nt][0] + b0, 0.f));
                r0.y = to_tf32(fmaxf(acc[mt][nt][1] + b1, 0.f));
                r1.x = to_tf32(fmaxf(acc[mt][nt][2] + b0, 0.f));
                r1.y = to_tf32(fmaxf(acc[mt][nt][3] + b1, 0.f));
            } else {
                r0.x = 1.f / (1.f + __expf(-(acc[mt][nt][0] + b0)));
                r0.y = 1.f / (1.f + __expf(-(acc[mt][nt][1] + b1)));
                r1.x = 1.f / (1.f + __expf(-(acc[mt][nt][2] + b0)));
                r1.y = 1.f / (1.f + __expf(-(acc[mt][nt][3] + b1)));
            }
            *(float2*)&C[(size_t)m0 * ldc + n0]       = r0;
            *(float2*)&C[(size_t)(m0 + 8) * ldc + n0] = r1;
        }
    }
}

// ============================================================================
extern "C" void kernel_launch(void* const* d_in, const int* in_sizes, int n_in,
                              void* d_out, int out_size)
{
    const float* x   = (const float*)d_in[0];
    const float* w1  = (const float*)d_in[1];
    const float* b1  = (const float*)d_in[2];
    const float* g1  = (const float*)d_in[3];
    const float* be1 = (const float*)d_in[4];
    const float* m1  = (const float*)d_in[5];
    const float* v1  = (const float*)d_in[6];
    const float* w2  = (const float*)d_in[7];
    const float* b2  = (const float*)d_in[8];
    const float* g2  = (const float*)d_in[9];
    const float* be2 = (const float*)d_in[10];
    const float* m2  = (const float*)d_in[11];
    const float* v2  = (const float*)d_in[12];
    const float* wa  = (const float*)d_in[13];
    const float* ba  = (const float*)d_in[14];
    const float* wd1 = (const float*)d_in[15];
    const float* bd1 = (const float*)d_in[16];
    const float* wd2 = (const float*)d_in[17];
    const float* bd2 = (const float*)d_in[18];
    float* out = (float*)d_out;

    const int fused_smem = FU_TOTAL * 4;                    // 227,008 B
    const int gemm_smem  = GSTAGE * GSTRIDE * 2 * 4;        // 98,304 B
    cudaFuncSetAttribute(conv_fused_kernel,
                         cudaFuncAttributeMaxDynamicSharedMemorySize, fused_smem);
    cudaFuncSetAttribute(gemm_tf32_kernel<4096, 0>,
                         cudaFuncAttributeMaxDynamicSharedMemorySize, gemm_smem);
    cudaFuncSetAttribute(gemm_tf32_kernel<512, 1>,
                         cudaFuncAttributeMaxDynamicSharedMemorySize, gemm_smem);

    cvt_all_kernel<<<2199, 256>>>(wd1, wd2, w2, w1);

    conv_fused_kernel<<<148, 256, fused_smem>>>(x, b1, g1, be1, m1, v1,
                                                b2, g2, be2, m2, v2, wa, ba);

    dim3 grid_fc1(4, 64);
    gemm_tf32_kernel<4096, 0><<<grid_fc1, 256, gemm_smem>>>(bd1, out);
    dim3 grid_fc2(1, 64);
    gemm_tf32_kernel<512, 1><<<grid_fc2, 256, gemm_smem>>>(bd2, out);
}

// round 13
// speedup vs baseline: 1.3757x; 1.2426x over previous
#include <cuda_runtime.h>
#include <cuda_bf16.h>
#include <math.h>
#include <stdint.h>

#define BN_EPS 1e-5f
#define BATCH 8192

// ---------------- scratch (device globals; no allocations allowed) ----------
__device__ __nv_bfloat16 g_fh[(size_t)BATCH * 4096];   // flattened feat, bf16 (67MB)
__device__ __nv_bfloat16 g_h1h[(size_t)BATCH * 512];   // fc1 output, bf16 (8MB)
__device__ __nv_bfloat16 g_wd1h[(size_t)512 * 4096];   // bf16 wd1 (4MB)
__device__ __nv_bfloat16 g_wd2h[(size_t)128 * 512];    // bf16 wd2
__device__ float g_wq[(size_t)9 * 64 * 36];            // conv2 W [q][oc][ic pad36] tf32
__device__ float g_w1q[(size_t)15 * 32 * 8];           // conv1 W [tap][oc][kx pad8] tf32

__device__ __forceinline__ float to_tf32(float x) {
    uint32_t r;
    asm("cvt.rna.tf32.f32 %0, %1;" : "=r"(r) : "f"(x));
    return __uint_as_float(r);
}

__device__ __forceinline__ void mma_tf32(float* c, float2 a02, float2 a13, float2 b)
{
    asm volatile(
        "mma.sync.aligned.m16n8k8.row.col.f32.tf32.tf32.f32 "
        "{%0,%1,%2,%3}, {%4,%5,%6,%7}, {%8,%9}, {%0,%1,%2,%3};\n"
        : "+f"(c[0]), "+f"(c[1]), "+f"(c[2]), "+f"(c[3])
        : "r"(__float_as_uint(a02.x)), "r"(__float_as_uint(a13.x)),
          "r"(__float_as_uint(a02.y)), "r"(__float_as_uint(a13.y)),
          "r"(__float_as_uint(b.x)),   "r"(__float_as_uint(b.y)));
}

// bf16 m16n8k16: a0 = row g k-lo, a1 = row g+8 k-lo, a2 = row g k-hi, a3 = row g+8 k-hi
__device__ __forceinline__ void mma_bf16(float* c, uint2 arow_g, uint2 arow_g8, uint2 b)
{
    asm volatile(
        "mma.sync.aligned.m16n8k16.row.col.f32.bf16.bf16.f32 "
        "{%0,%1,%2,%3}, {%4,%5,%6,%7}, {%8,%9}, {%0,%1,%2,%3};\n"
        : "+f"(c[0]), "+f"(c[1]), "+f"(c[2]), "+f"(c[3])
        : "r"(arow_g.x), "r"(arow_g8.x), "r"(arow_g.y), "r"(arow_g8.y),
          "r"(b.x), "r"(b.y));
}

__device__ __forceinline__ void cp_async16(uint32_t dst_smem, const void* src) {
    asm volatile("cp.async.cg.shared.global [%0], [%1], 16;\n"
                 :: "r"(dst_smem), "l"(src));
}
__device__ __forceinline__ void cp_async8(uint32_t dst_smem, const void* src) {
    asm volatile("cp.async.ca.shared.global [%0], [%1], 8;\n"
                 :: "r"(dst_smem), "l"(src));
}
__device__ __forceinline__ void cp_commit() {
    asm volatile("cp.async.commit_group;\n" ::: "memory");
}
template<int N>
__device__ __forceinline__ void cp_wait() {
    asm volatile("cp.async.wait_group %0;\n" :: "n"(N) : "memory");
}

#define BARG(grp) asm volatile("bar.sync %0, 128;" :: "r"((grp) + 1) : "memory")

// ============================================================================
// Merged prep kernel: wd1->bf16, wd2->bf16, w2->tf32, w1->tf32.
// blocks [0,2048): wd1 | [2048,2112): wd2 | [2112,2184): w2 | [2184,2199): w1
// ============================================================================
__global__ __launch_bounds__(256) void cvt_all_kernel(
    const float* __restrict__ wd1, const float* __restrict__ wd2,
    const float* __restrict__ w2,  const float* __restrict__ w1)
{
    const int b = blockIdx.x, t = threadIdx.x;
    if (b < 2048) {
        int i = b * 256 + t;                 // 524288 float4
        float4 v = ((const float4*)wd1)[i];
        __nv_bfloat162 lo = __floats2bfloat162_rn(v.x, v.y);
        __nv_bfloat162 hi = __floats2bfloat162_rn(v.z, v.w);
        ((__nv_bfloat162*)g_wd1h)[i * 2]     = lo;
        ((__nv_bfloat162*)g_wd1h)[i * 2 + 1] = hi;
    } else if (b < 2112) {
        int i = (b - 2048) * 256 + t;        // 16384 float4
        float4 v = ((const float4*)wd2)[i];
        __nv_bfloat162 lo = __floats2bfloat162_rn(v.x, v.y);
        __nv_bfloat162 hi = __floats2bfloat162_rn(v.z, v.w);
        ((__nv_bfloat162*)g_wd2h)[i * 2]     = lo;
        ((__nv_bfloat162*)g_wd2h)[i * 2 + 1] = hi;
    } else if (b < 2184) {
        int i = (b - 2112) * 256 + t;        // 18432 = 64*32*9
        if (i < 18432) {
            int oc = i / 288;
            int rem = i % 288;
            int ic = rem / 9;
            int q  = rem % 9;
            g_wq[(q * 64 + oc) * 36 + ic] = to_tf32(w2[i]);
        }
    } else {
        int i = (b - 2184) * 256 + t;        // 3840 = 15*32*8
        if (i < 3840) {
            int tap = i >> 8;
            int oc  = (i >> 3) & 31;
            int kx  = i & 7;
            int ic  = tap / 5, ky = tap % 5;
            float v = (kx < 5) ? w1[oc * 75 + ic * 25 + ky * 5 + kx] : 0.f;
            g_w1q[i] = to_tf32(v);
        }
    }
}

// ============================================================================
// FUSED conv1+conv2 (PROVEN R11; only change: final store is bf16 -> g_fh).
// ============================================================================
#define FU_WQ     0
#define FU_WB     20736
#define FU_HWC    24576
#define FU_XS     47904
#define FU_ATTN   56112
#define FU_SCR    56240
#define FU_SC1    56496
#define FU_BI1    56528
#define FU_SC2    56560
#define FU_BI2    56624
#define FU_WAS    56688
#define FU_TOTAL  56752

__global__ __launch_bounds__(256) void conv_fused_kernel(
    const float* __restrict__ x,
    const float* __restrict__ b1, const float* __restrict__ g1,
    const float* __restrict__ be1, const float* __restrict__ m1,
    const float* __restrict__ v1,
    const float* __restrict__ b2, const float* __restrict__ g2,
    const float* __restrict__ be2, const float* __restrict__ m2,
    const float* __restrict__ v2, const float* __restrict__ wa,
    const float* __restrict__ ba)
{
    extern __shared__ float sm[];
    float* wq   = sm + FU_WQ;
    float* wb   = sm + FU_WB;
    float* sc1  = sm + FU_SC1;
    float* bi1  = sm + FU_BI1;
    float* sc2  = sm + FU_SC2;
    float* bi2  = sm + FU_BI2;
    float* was  = sm + FU_WAS;

    const int t = threadIdx.x;

    for (int i = t; i < 20736; i += 256) wq[i] = g_wq[i];
    for (int i = t; i < 3840; i += 256) wb[i] = g_w1q[i];
    for (int i = t; i < 23328; i += 256) sm[FU_HWC + i] = 0.f;
    for (int i = t; i < 8208; i += 256) sm[FU_XS + i] = 0.f;   // xs borders persist
    if (t < 32) {
        float s = g1[t] * rsqrtf(v1[t] + BN_EPS);
        sc1[t] = s;
        bi1[t] = be1[t] + (b1[t] - m1[t]) * s;
    }
    if (t < 64) {
        float s = g2[t] * rsqrtf(v2[t] + BN_EPS);
        sc2[t] = s;
        bi2[t] = be2[t] + (b2[t] - m2[t]) * s;
        was[t] = wa[t];
    }
    const float bav = ba[0];
    __syncthreads();

    const int grp  = t >> 7;
    const int u    = t & 127;
    const int w4   = u >> 5;
    const int lane = u & 31;
    const int g    = lane >> 2, tg = lane & 3;
    const int wm   = w4 >> 1, wn = w4 & 1;

    float* hwc  = sm + FU_HWC + grp * 11664;
    float* feat = hwc;                          // aliases hwc[0:4096)
    float* xs   = sm + FU_XS + grp * 4104;
    float* attn = sm + FU_ATTN + grp * 64;
    float* scr  = sm + FU_SCR + grp * 128;
    const uint32_t xsU = (uint32_t)__cvta_generic_to_shared(xs);

    int baseA[2][2];
#pragma unroll
    for (int mt = 0; mt < 2; mt++)
#pragma unroll
        for (int r = 0; r < 2; r++) {
            int m = wm * 32 + mt * 16 + g + 8 * r;
            baseA[mt][r] = 36 * (m >> 3) + 2 * (m & 7);
        }

    const int stride = gridDim.x * 2;
    const int n0 = blockIdx.x * 2 + grp;

    if (n0 < BATCH) {
        const float* src = x + (size_t)n0 * 3072;
#pragma unroll
        for (int j = 0; j < 12; j++) {
            int i2 = 2 * (u + 128 * j);
            int ic = i2 >> 10, rem = i2 & 1023, iy = rem >> 5, ix = rem & 31;
            cp_async8(xsU + (ic * 1368 + (iy + 2) * 38 + ix + 2) * 4, src + i2);
        }
        cp_commit();
    }

    for (int n = n0; n < BATCH; n += stride) {
        cp_wait<0>();
#pragma unroll
        for (int j = 0; j < 12; j++) {
            int i2 = 2 * (u + 128 * j);
            int ic = i2 >> 10, rem = i2 & 1023, iy = rem >> 5, ix = rem & 31;
            float2* p = (float2*)(xs + ic * 1368 + (iy + 2) * 38 + ix + 2);
            float2 v = *p;
            v.x = to_tf32(v.x); v.y = to_tf32(v.y);
            *p = v;
        }
        BARG(grp);

        // ---- conv1 mma ----
        {
            float acc[4][4][4];
#pragma unroll
            for (int mt = 0; mt < 4; mt++)
#pragma unroll
                for (int nt = 0; nt < 4; nt++)
#pragma unroll
                    for (int i = 0; i < 4; i++) acc[mt][nt][i] = 0.f;

#pragma unroll
            for (int tap = 0; tap < 15; tap++) {
                const int ic = tap / 5, ky = tap % 5;
                const float* Bp = wb + tap * 256 + g * 8 + 2 * tg;
                float2 bf[4];
#pragma unroll
                for (int nt = 0; nt < 4; nt++)
                    bf[nt] = *(const float2*)(Bp + nt * 64);
#pragma unroll
                for (int mt = 0; mt < 4; mt++) {
                    const int oy = (w4 << 2) + mt;
                    const float* Ap = xs + ic * 1368 + (2 * oy + ky) * 38 + 2 * tg;
                    float2 a0 = *(const float2*)(Ap + 2 * g);
                    float2 a1 = *(const float2*)(Ap + 2 * g + 16);
#pragma unroll
                    for (int nt = 0; nt < 4; nt++)
                        mma_tf32(acc[mt][nt], a0, a1, bf[nt]);
                }
            }
            BARG(grp);   // xs reads done -> safe to prefetch into xs

#pragma unroll
            for (int mt = 0; mt < 4; mt++) {
                const int oy = (w4 << 2) + mt;
#pragma unroll
                for (int nt = 0; nt < 4; nt++) {
                    const int oc = nt * 8 + 2 * tg;
                    const float s0 = sc1[oc], s1 = sc1[oc + 1];
                    const float t0 = bi1[oc], t1 = bi1[oc + 1];
                    float2 r0, r1;
                    r0.x = to_tf32(fmaxf(acc[mt][nt][0] * s0 + t0, 0.f));
                    r0.y = to_tf32(fmaxf(acc[mt][nt][1] * s1 + t1, 0.f));
                    r1.x = to_tf32(fmaxf(acc[mt][nt][2] * s0 + t0, 0.f));
                    r1.y = to_tf32(fmaxf(acc[mt][nt][3] * s1 + t1, 0.f));
                    *(float2*)&hwc[((oy + 1) * 18 + g + 1) * 36 + oc] = r0;
                    *(float2*)&hwc[((oy + 1) * 18 + g + 9) * 36 + oc] = r1;
                }
            }
            // re-zero border cells inside feat region [0, 4096)
            for (int jj = u; jj < 1044; jj += 128) {
                int j = jj / 36, ic = jj % 36;
                int pos;
                if (j < 18)      pos = j;
                else if (j < 28) { int r = j - 18; pos = (r / 2 + 1) * 18 + (r & 1) * 17; }
                else             pos = 108;
                hwc[pos * 36 + ic] = 0.f;
            }
            const int n_next = n + stride;
            if (n_next < BATCH) {
                const float* src = x + (size_t)n_next * 3072;
#pragma unroll
                for (int j = 0; j < 12; j++) {
                    int i2 = 2 * (u + 128 * j);
                    int ic = i2 >> 10, rem = i2 & 1023, iy = rem >> 5, ix = rem & 31;
                    cp_async8(xsU + (ic * 1368 + (iy + 2) * 38 + ix + 2) * 4, src + i2);
                }
                cp_commit();
            }
        }
        BARG(grp);   // hwc ready

        // ---- conv2 mma ----
        float acc[2][4][4];
#pragma unroll
        for (int mt = 0; mt < 2; mt++)
#pragma unroll
            for (int nt = 0; nt < 4; nt++)
#pragma unroll
                for (int i = 0; i < 4; i++) acc[mt][nt][i] = 0.f;

        for (int q = 0; q < 9; q++) {
            const int kh = q / 3, kw = q - kh * 3;
            const int dq = kh * 18 + kw;
            const float* A00 = hwc + (baseA[0][0] + dq) * 36 + 2 * tg;
            const float* A01 = hwc + (baseA[0][1] + dq) * 36 + 2 * tg;
            const float* A10 = hwc + (baseA[1][0] + dq) * 36 + 2 * tg;
            const float* A11 = hwc + (baseA[1][1] + dq) * 36 + 2 * tg;
            const float* Bq  = wq + (q * 64 + wn * 32 + g) * 36 + 2 * tg;
#pragma unroll
            for (int kk = 0; kk < 32; kk += 8) {
                float2 af[2][2], bf[4];
                af[0][0] = *(const float2*)(A00 + kk);
                af[0][1] = *(const float2*)(A01 + kk);
                af[1][0] = *(const float2*)(A10 + kk);
                af[1][1] = *(const float2*)(A11 + kk);
#pragma unroll
                for (int nt = 0; nt < 4; nt++)
                    bf[nt] = *(const float2*)(Bq + nt * (8 * 36) + kk);
#pragma unroll
                for (int mt = 0; mt < 2; mt++)
#pragma unroll
                    for (int nt = 0; nt < 4; nt++)
                        mma_tf32(acc[mt][nt], af[mt][0], af[mt][1], bf[nt]);
            }
        }
        BARG(grp);   // hwc reads done (incl. feat region)

        // BN + ReLU -> feat[oc][pos]
#pragma unroll
        for (int mt = 0; mt < 2; mt++) {
            const int m0 = wm * 32 + mt * 16 + g;
#pragma unroll
            for (int nt = 0; nt < 4; nt++) {
                const int c0 = wn * 32 + nt * 8 + 2 * tg;
                float s0 = sc2[c0], s1 = sc2[c0 + 1];
                float t0 = bi2[c0], t1 = bi2[c0 + 1];
                feat[c0 * 64 + m0]           = fmaxf(acc[mt][nt][0] * s0 + t0, 0.f);
                feat[(c0 + 1) * 64 + m0]     = fmaxf(acc[mt][nt][1] * s1 + t1, 0.f);
                feat[c0 * 64 + m0 + 8]       = fmaxf(acc[mt][nt][2] * s0 + t0, 0.f);
                feat[(c0 + 1) * 64 + m0 + 8] = fmaxf(acc[mt][nt][3] * s1 + t1, 0.f);
            }
        }
        BARG(grp);

        // Haar cD * upsample
        for (int qq = u; qq < 1024; qq += 128) {
            int c = qq >> 4, blk = qq & 15;
            int bI = blk >> 2, bJ = blk & 3;
            int p00 = c * 64 + (bI * 2) * 8 + bJ * 2;
            float a = feat[p00], b = feat[p00 + 1];
            float cc = feat[p00 + 8], d = feat[p00 + 9];
            float v = (a - b - cc + d) * 0.5f;
            feat[p00]     = a  * v;
            feat[p00 + 1] = b  * v;
            feat[p00 + 8] = cc * v;
            feat[p00 + 9] = d  * v;
        }
        BARG(grp);

        // 1x1 attn: two 32-channel partial sums per output
        {
            const int half = u >> 6, uu = u & 63;
            float s = (half == 0) ? bav : 0.f;
            const int cb = half * 32;
#pragma unroll 8
            for (int c = 0; c < 32; c++)
                s += feat[(cb + c) * 64 + uu] * was[cb + c];
            scr[half * 64 + uu] = s;
        }
        BARG(grp);
        if (u < 64) {
            float s = scr[u] + scr[64 + u];
            attn[u] = 1.f / (1.f + __expf(-s));
        }
        BARG(grp);

        // multiply & store bf16 (feeds bf16 fc1)
        __nv_bfloat162* fg2 = (__nv_bfloat162*)(g_fh + (size_t)n * 4096);
        for (int i = 2 * u; i < 4096; i += 256) {
            float v0 = feat[i] * attn[i & 63];
            float v1 = feat[i + 1] * attn[(i + 1) & 63];
            fg2[i >> 1] = __floats2bfloat162_rn(v0, v1);
        }
        BARG(grp);   // feat reads done; next iter may overwrite hwc
    }
}

// ============================================================================
// bf16 GEMM: 128x128 tile, 256 threads (8 warps, warp tile 32x64),
// m16n8k16, cp.async 4-stage, distance-3 prefetch, ONE barrier per k16.
// Row stride 16 bf16 = 32 B: rows mod 4 tile the 4 bank groups -> fragment
// LDS.64 conflict-free (half-warp phase model).
// k-permutation: slot pairs {2tg,2tg+1}/{2tg+8,2tg+9} <- mem {4tg..4tg+3},
// applied to A and B identically (contraction invariant).
// FIXED vs R12: A mt-tile offset is mt*256 elems (16 rows x 16), NOT mt*512.
// MODE 0: g_h1h = bf16(relu(g_fh @ g_wd1h^T + bias))
// MODE 1: out   = sigmoid(g_h1h @ g_wd2h^T + bias)   (float out)
// ============================================================================
#define GSTAGE 4
#define GSTRIDE_H 2048          // bf16 elems per stage: 128 rows * 16

template<int KDIM, int MODE>
__global__ __launch_bounds__(256, 2) void gemm_bf16_kernel(
    const float* __restrict__ bias, float* __restrict__ Cout)
{
    const __nv_bfloat16* A = (MODE == 0) ? g_fh  : g_h1h;
    const __nv_bfloat16* B = (MODE == 0) ? g_wd1h : g_wd2h;

    extern __shared__ __nv_bfloat16 smh[];
    __nv_bfloat16* As = smh;                          // [4][2048]
    __nv_bfloat16* Bs = smh + GSTAGE * GSTRIDE_H;     // [4][2048]
    const uint32_t AsU = (uint32_t)__cvta_generic_to_shared(As);
    const uint32_t BsU = (uint32_t)__cvta_generic_to_shared(Bs);

    const int t  = threadIdx.x;
    const int bn = blockIdx.x, bm = blockIdx.y;
    const int w  = t >> 5, lane = t & 31;
    const int wm = w >> 1, wn = w & 1;      // 4 x 2 warp grid, warp tile 32x64
    const int g  = lane >> 2, tg = lane & 3;

    // cp.async: thread t loads 16B = 8 bf16 = half a row per matrix per stage
    const int lrow = t >> 1, lhalf = t & 1;
    const __nv_bfloat16* PA = A + (size_t)(bm * 128 + lrow) * KDIM + lhalf * 8;
    const __nv_bfloat16* PB = B + (size_t)(bn * 128 + lrow) * KDIM + lhalf * 8;
    const uint32_t DA = AsU + (lrow * 16 + lhalf * 8) * 2;
    const uint32_t DB = BsU + (lrow * 16 + lhalf * 8) * 2;

    const int NIT = KDIM / 16;

#pragma unroll
    for (int s = 0; s < 3; s++) {
        cp_async16(DA + s * (GSTRIDE_H * 2), PA + s * 16);
        cp_async16(DB + s * (GSTRIDE_H * 2), PB + s * 16);
        cp_commit();
    }

    float acc[2][8][4];
#pragma unroll
    for (int mt = 0; mt < 2; mt++)
#pragma unroll
        for (int nt = 0; nt < 8; nt++)
#pragma unroll
            for (int i = 0; i < 4; i++) acc[mt][nt][i] = 0.f;

    // fragment smem offsets (bf16 elems): row*16 + 4tg
    const int arow0 = (wm * 32 + g) * 16 + 4 * tg;     // +mt*256, +128 for row+8
    const int brow0 = (wn * 64 + g) * 16 + 4 * tg;     // +nt*128

#pragma unroll 1
    for (int it = 0; it < NIT; it++) {
        if (it < NIT - 2)       cp_wait<2>();
        else if (it == NIT - 2) cp_wait<1>();
        else                    cp_wait<0>();
        __syncthreads();

        if (it + 3 < NIT) {
            const int sn = (it + 3) & 3;
            cp_async16(DA + sn * (GSTRIDE_H * 2), PA + (it + 3) * 16);
            cp_async16(DB + sn * (GSTRIDE_H * 2), PB + (it + 3) * 16);
            cp_commit();
        }

        const int s = it & 3;
        const __nv_bfloat16* Ab = As + s * GSTRIDE_H;
        const __nv_bfloat16* Bb = Bs + s * GSTRIDE_H;

        uint2 afg[2], afg8[2], bf[8];
#pragma unroll
        for (int mt = 0; mt < 2; mt++) {
            afg[mt]  = *(const uint2*)(Ab + arow0 + mt * 256);
            afg8[mt] = *(const uint2*)(Ab + arow0 + mt * 256 + 128);
        }
#pragma unroll
        for (int nt = 0; nt < 8; nt++)
            bf[nt] = *(const uint2*)(Bb + brow0 + nt * 128);
#pragma unroll
        for (int mt = 0; mt < 2; mt++)
#pragma unroll
            for (int nt = 0; nt < 8; nt++)
                mma_bf16(acc[mt][nt], afg[mt], afg8[mt], bf[nt]);
    }

#pragma unroll
    for (int mt = 0; mt < 2; mt++) {
        const int m0 = bm * 128 + wm * 32 + mt * 16 + g;
#pragma unroll
        for (int nt = 0; nt < 8; nt++) {
            const int n0 = bn * 128 + wn * 64 + nt * 8 + 2 * tg;
            const float b0 = bias[n0], b1 = bias[n0 + 1];
            if (MODE == 0) {
                __nv_bfloat162 r0 = __floats2bfloat162_rn(
                    fmaxf(acc[mt][nt][0] + b0, 0.f), fmaxf(acc[mt][nt][1] + b1, 0.f));
                __nv_bfloat162 r1 = __floats2bfloat162_rn(
                    fmaxf(acc[mt][nt][2] + b0, 0.f), fmaxf(acc[mt][nt][3] + b1, 0.f));
                *(__nv_bfloat162*)&g_h1h[(size_t)m0 * 512 + n0]       = r0;
                *(__nv_bfloat162*)&g_h1h[(size_t)(m0 + 8) * 512 + n0] = r1;
            } else {
                float2 r0, r1;
                r0.x = 1.f / (1.f + __expf(-(acc[mt][nt][0] + b0)));
                r0.y = 1.f / (1.f + __expf(-(acc[mt][nt][1] + b1)));
                r1.x = 1.f / (1.f + __expf(-(acc[mt][nt][2] + b0)));
                r1.y = 1.f / (1.f + __expf(-(acc[mt][nt][3] + b1)));
                *(float2*)&Cout[(size_t)m0 * 128 + n0]       = r0;
                *(float2*)&Cout[(size_t)(m0 + 8) * 128 + n0] = r1;
            }
        }
    }
}

// ============================================================================
extern "C" void kernel_launch(void* const* d_in, const int* in_sizes, int n_in,
                              void* d_out, int out_size)
{
    const float* x   = (const float*)d_in[0];
    const float* w1  = (const float*)d_in[1];
    const float* b1  = (const float*)d_in[2];
    const float* g1  = (const float*)d_in[3];
    const float* be1 = (const float*)d_in[4];
    const float* m1  = (const float*)d_in[5];
    const float* v1  = (const float*)d_in[6];
    const float* w2  = (const float*)d_in[7];
    const float* b2  = (const float*)d_in[8];
    const float* g2  = (const float*)d_in[9];
    const float* be2 = (const float*)d_in[10];
    const float* m2  = (const float*)d_in[11];
    const float* v2  = (const float*)d_in[12];
    const float* wa  = (const float*)d_in[13];
    const float* ba  = (const float*)d_in[14];
    const float* wd1 = (const float*)d_in[15];
    const float* bd1 = (const float*)d_in[16];
    const float* wd2 = (const float*)d_in[17];
    const float* bd2 = (const float*)d_in[18];
    float* out = (float*)d_out;

    const int fused_smem = FU_TOTAL * 4;                    // 227,008 B
    const int gemm_smem  = GSTAGE * GSTRIDE_H * 2 * 2;      // 32,768 B
    cudaFuncSetAttribute(conv_fused_kernel,
                         cudaFuncAttributeMaxDynamicSharedMemorySize, fused_smem);
    cudaFuncSetAttribute(gemm_bf16_kernel<4096, 0>,
                         cudaFuncAttributeMaxDynamicSharedMemorySize, gemm_smem);
    cudaFuncSetAttribute(gemm_bf16_kernel<512, 1>,
                         cudaFuncAttributeMaxDynamicSharedMemorySize, gemm_smem);

    cvt_all_kernel<<<2199, 256>>>(wd1, wd2, w2, w1);

    conv_fused_kernel<<<148, 256, fused_smem>>>(x, b1, g1, be1, m1, v1,
                                                b2, g2, be2, m2, v2, wa, ba);

    dim3 grid_fc1(4, 64);
    gemm_bf16_kernel<4096, 0><<<grid_fc1, 256, gemm_smem>>>(bd1, out);
    dim3 grid_fc2(1, 64);
    gemm_bf16_kernel<512, 1><<<grid_fc2, 256, gemm_smem>>>(bd2, out);
}

// round 14
// speedup vs baseline: 1.8555x; 1.3488x over previous
#include <cuda_runtime.h>
#include <cuda_bf16.h>
#include <math.h>
#include <stdint.h>

#define BN_EPS 1e-5f
#define BATCH 8192

// ---------------- scratch (device globals; no allocations allowed) ----------
__device__ __nv_bfloat16 g_fh[(size_t)BATCH * 4096];   // flattened feat, bf16 (67MB)
__device__ __nv_bfloat16 g_h1h[(size_t)BATCH * 512];   // fc1 output, bf16 (8MB)
__device__ __nv_bfloat16 g_wd1h[(size_t)512 * 4096];   // bf16 wd1 (4MB)
__device__ __nv_bfloat16 g_wd2h[(size_t)128 * 512];    // bf16 wd2
__device__ __nv_bfloat16 g_wqh[(size_t)9 * 64 * 48];   // conv2 W [q][oc][ic pad48] bf16
__device__ __nv_bfloat16 g_w1h[(size_t)10 * 32 * 16];  // conv1 W [ky*2+h][oc][(px,ic4) 16] bf16

__device__ __forceinline__ void mma_bf16(float* c, uint2 arow_g, uint2 arow_g8, uint2 b)
{
    asm volatile(
        "mma.sync.aligned.m16n8k16.row.col.f32.bf16.bf16.f32 "
        "{%0,%1,%2,%3}, {%4,%5,%6,%7}, {%8,%9}, {%0,%1,%2,%3};\n"
        : "+f"(c[0]), "+f"(c[1]), "+f"(c[2]), "+f"(c[3])
        : "r"(arow_g.x), "r"(arow_g8.x), "r"(arow_g.y), "r"(arow_g8.y),
          "r"(b.x), "r"(b.y));
}

__device__ __forceinline__ void cp_async16(uint32_t dst_smem, const void* src) {
    asm volatile("cp.async.cg.shared.global [%0], [%1], 16;\n"
                 :: "r"(dst_smem), "l"(src));
}
__device__ __forceinline__ void cp_commit() {
    asm volatile("cp.async.commit_group;\n" ::: "memory");
}
template<int N>
__device__ __forceinline__ void cp_wait() {
    asm volatile("cp.async.wait_group %0;\n" :: "n"(N) : "memory");
}

#define BARG(grp) asm volatile("bar.sync %0, 128;" :: "r"((grp) + 1) : "memory")

// ============================================================================
// Merged prep: wd1->bf16 | wd2->bf16 | w2->wqh bf16 | w1->w1h bf16
// blocks [0,2048) | [2048,2112) | [2112,2184) | [2184,2204)
// ============================================================================
__global__ __launch_bounds__(256) void cvt_all_kernel(
    const float* __restrict__ wd1, const float* __restrict__ wd2,
    const float* __restrict__ w2,  const float* __restrict__ w1)
{
    const int b = blockIdx.x, t = threadIdx.x;
    if (b < 2048) {
        int i = b * 256 + t;                 // 524288 float4
        float4 v = ((const float4*)wd1)[i];
        ((__nv_bfloat162*)g_wd1h)[i * 2]     = __floats2bfloat162_rn(v.x, v.y);
        ((__nv_bfloat162*)g_wd1h)[i * 2 + 1] = __floats2bfloat162_rn(v.z, v.w);
    } else if (b < 2112) {
        int i = (b - 2048) * 256 + t;        // 16384 float4
        float4 v = ((const float4*)wd2)[i];
        ((__nv_bfloat162*)g_wd2h)[i * 2]     = __floats2bfloat162_rn(v.x, v.y);
        ((__nv_bfloat162*)g_wd2h)[i * 2 + 1] = __floats2bfloat162_rn(v.z, v.w);
    } else if (b < 2184) {
        int i = (b - 2112) * 256 + t;        // 18432 = 64*32*9
        if (i < 18432) {
            int oc = i / 288;
            int rem = i % 288;
            int ic = rem / 9;
            int q  = rem % 9;
            g_wqh[(q * 64 + oc) * 48 + ic] = __float2bfloat16_rn(w2[i]);
            // pads [32..47] stay zero (global zero-init, never written)
        }
    } else {
        int i = (b - 2184) * 256 + t;        // 5120 = 10*32*16
        if (i < 5120) {
            int j  = i & 15;                 // (pixel, ic) packed
            int r  = i >> 4;                 // row: kyh*32 + oc
            int oc = r & 31;
            int kyh = r >> 5;                // ky*2 + h
            int ky = kyh >> 1, h = kyh & 1;
            int p  = j >> 2, ic = j & 3;
            int kx = 4 * h + p;
            float v = (ic < 3 && kx < 5) ? w1[oc * 75 + ic * 25 + ky * 5 + kx] : 0.f;
            g_w1h[i] = __float2bfloat16_rn(v);
        }
    }
}

// ============================================================================
// FUSED conv1+conv2, all-bf16 tensor path.
// 256 thr = 2 independent 128-thr groups (named barriers), persistent.
//
// conv1: k16 = 4 pixels x 4 ic(pad); per (ky, kxhalf h): A rows = contiguous
//        16-bf16 windows of xs[iy][ix][ic4]; 10 taps x 16 mma.
// conv2: hwc [pixel 18x18][ic32] stride-40 bf16; k16 x 2 per tap q.
// Bank analysis (half-warp phase model): hwc per-g bank step 8 (2 rows x 40),
// wq stride 48 -> step 24, conv1 A windows span <128B, conv1 B stride 16 ->
// step 8 — all conflict-free.
//
// smem bytes: wqh 55296 | wbh 10240 | hwc 2x25920 | xs 2x10944 |
//             stage 2x12288 (f32) | feat 2x16384 (f32) | attn/scr/consts
// ============================================================================
#define OF_WQH   0
#define OF_WBH   55296
#define OF_HWC   65536
#define OF_XS    117376
#define OF_STG   139264
#define OF_FEAT  163840
#define OF_ATTN  196608
#define OF_SCR   197120
#define OF_CON   198144
#define FU_BYTES 199168

__global__ __launch_bounds__(256) void conv_fused_kernel(
    const float* __restrict__ x,
    const float* __restrict__ b1, const float* __restrict__ g1,
    const float* __restrict__ be1, const float* __restrict__ m1,
    const float* __restrict__ v1,
    const float* __restrict__ b2, const float* __restrict__ g2,
    const float* __restrict__ be2, const float* __restrict__ m2,
    const float* __restrict__ v2, const float* __restrict__ wa,
    const float* __restrict__ ba)
{
    extern __shared__ char smc[];
    __nv_bfloat16* wqh = (__nv_bfloat16*)(smc + OF_WQH);
    __nv_bfloat16* wbh = (__nv_bfloat16*)(smc + OF_WBH);
    float* sc1 = (float*)(smc + OF_CON);
    float* bi1 = sc1 + 32;
    float* sc2 = bi1 + 32;
    float* bi2 = sc2 + 64;
    float* was = bi2 + 64;

    const int t = threadIdx.x;

    for (int i = t; i < 13824; i += 256) ((uint32_t*)wqh)[i] = ((const uint32_t*)g_wqh)[i];
    for (int i = t; i < 2560; i += 256)  ((uint32_t*)wbh)[i] = ((const uint32_t*)g_w1h)[i];
    for (int i = t; i < 12960; i += 256) ((uint32_t*)(smc + OF_HWC))[i] = 0;  // borders persist
    for (int i = t; i < 5472; i += 256)  ((uint32_t*)(smc + OF_XS))[i] = 0;   // borders + ic-pad persist
    if (t < 32) {
        float s = g1[t] * rsqrtf(v1[t] + BN_EPS);
        sc1[t] = s;
        bi1[t] = be1[t] + (b1[t] - m1[t]) * s;
    }
    if (t < 64) {
        float s = g2[t] * rsqrtf(v2[t] + BN_EPS);
        sc2[t] = s;
        bi2[t] = be2[t] + (b2[t] - m2[t]) * s;
        was[t] = wa[t];
    }
    const float bav = ba[0];
    __syncthreads();

    const int grp  = t >> 7;
    const int u    = t & 127;
    const int w4   = u >> 5;
    const int lane = u & 31;
    const int g    = lane >> 2, tg = lane & 3;
    const int wm   = w4 >> 1, wn = w4 & 1;

    __nv_bfloat16* hwc = (__nv_bfloat16*)(smc + OF_HWC) + grp * 12960;  // stride 40/pixel
    __nv_bfloat16* xs  = (__nv_bfloat16*)(smc + OF_XS)  + grp * 5472;   // [36][38][4]
    float* stage = (float*)(smc + OF_STG)  + grp * 3072;
    float* feat  = (float*)(smc + OF_FEAT) + grp * 4096;
    float* attn  = (float*)(smc + OF_ATTN) + grp * 64;
    float* scr   = (float*)(smc + OF_SCR)  + grp * 128;
    const uint32_t stgU = (uint32_t)__cvta_generic_to_shared(stage);

    int baseA[2][2];    // pixel index within 18x18 padded grid
#pragma unroll
    for (int mt = 0; mt < 2; mt++)
#pragma unroll
        for (int r = 0; r < 2; r++) {
            int m = wm * 32 + mt * 16 + g + 8 * r;
            baseA[mt][r] = 36 * (m >> 3) + 2 * (m & 7);
        }

    const int stride = gridDim.x * 2;
    const int n0 = blockIdx.x * 2 + grp;

    if (n0 < BATCH) {
        const float* src = x + (size_t)n0 * 3072;
#pragma unroll
        for (int c = 0; c < 6; c++) {
            int idx = u + 128 * c;
            cp_async16(stgU + idx * 16, src + idx * 4);
        }
        cp_commit();
    }

    for (int n = n0; n < BATCH; n += stride) {
        // ---- publish: stage f32 NCHW -> xs bf16 [iy][ix][ic4] ----
        cp_wait<0>();
#pragma unroll
        for (int j = 0; j < 8; j++) {
            int p = u + 128 * j;          // pixel 0..1023
            int iy = p >> 5, ix = p & 31;
            float f0 = stage[p];
            float f1 = stage[1024 + p];
            float f2 = stage[2048 + p];
            __nv_bfloat162 lo = __floats2bfloat162_rn(f0, f1);
            __nv_bfloat162 hi = __floats2bfloat162_rn(f2, 0.f);
            uint2 val = { *(uint32_t*)&lo, *(uint32_t*)&hi };
            *(uint2*)(xs + ((iy + 2) * 38 + ix + 2) * 4) = val;
        }
        BARG(grp);

        // ---- conv1 mma (bf16): 10 taps (ky,h), k16 = 4px x 4ic ----
        {
            float acc[4][4][4];
#pragma unroll
            for (int mt = 0; mt < 4; mt++)
#pragma unroll
                for (int nt = 0; nt < 4; nt++)
#pragma unroll
                    for (int i = 0; i < 4; i++) acc[mt][nt][i] = 0.f;

#pragma unroll
            for (int ky = 0; ky < 5; ky++) {
#pragma unroll
                for (int h = 0; h < 2; h++) {
                    const __nv_bfloat16* Bp = wbh + ((ky * 2 + h) * 32 + g) * 16 + 4 * tg;
                    uint2 bf[4];
#pragma unroll
                    for (int nt = 0; nt < 4; nt++)
                        bf[nt] = *(const uint2*)(Bp + nt * 128);
#pragma unroll
                    for (int mt = 0; mt < 4; mt++) {
                        const int oy = (w4 << 2) + mt;
                        const __nv_bfloat16* Ap =
                            xs + (2 * oy + ky) * 152 + (2 * g + 4 * h) * 4 + 4 * tg;
                        uint2 a0 = *(const uint2*)Ap;          // pos ox=g
                        uint2 a1 = *(const uint2*)(Ap + 64);   // pos ox=g+8
#pragma unroll
                        for (int nt = 0; nt < 4; nt++)
                            mma_bf16(acc[mt][nt], a0, a1, bf[nt]);
                    }
                }
            }

            // epilogue: BN + ReLU -> hwc bf16; prefetch next image into stage
#pragma unroll
            for (int mt = 0; mt < 4; mt++) {
                const int oy = (w4 << 2) + mt;
#pragma unroll
                for (int nt = 0; nt < 4; nt++) {
                    const int oc = nt * 8 + 2 * tg;
                    const float s0 = sc1[oc], s1 = sc1[oc + 1];
                    const float t0 = bi1[oc], t1 = bi1[oc + 1];
                    __nv_bfloat162 r0 = __floats2bfloat162_rn(
                        fmaxf(acc[mt][nt][0] * s0 + t0, 0.f),
                        fmaxf(acc[mt][nt][1] * s1 + t1, 0.f));
                    __nv_bfloat162 r1 = __floats2bfloat162_rn(
                        fmaxf(acc[mt][nt][2] * s0 + t0, 0.f),
                        fmaxf(acc[mt][nt][3] * s1 + t1, 0.f));
                    const int p0 = (oy + 1) * 18 + g + 1;
                    *(__nv_bfloat162*)(hwc + p0 * 40 + oc)       = r0;
                    *(__nv_bfloat162*)(hwc + (p0 + 8) * 40 + oc) = r1;
                }
            }
            const int n_next = n + stride;
            if (n_next < BATCH) {
                const float* src = x + (size_t)n_next * 3072;
#pragma unroll
                for (int c = 0; c < 6; c++) {
                    int idx = u + 128 * c;
                    cp_async16(stgU + idx * 16, src + idx * 4);
                }
                cp_commit();
            }
        }
        BARG(grp);   // hwc ready

        // ---- conv2 mma (bf16): 9 taps x 2 k16 ----
        float acc[2][4][4];
#pragma unroll
        for (int mt = 0; mt < 2; mt++)
#pragma unroll
            for (int nt = 0; nt < 4; nt++)
#pragma unroll
                for (int i = 0; i < 4; i++) acc[mt][nt][i] = 0.f;

        for (int q = 0; q < 9; q++) {
            const int kh = q / 3, kw = q - kh * 3;
            const int dq = kh * 18 + kw;
#pragma unroll
            for (int k2 = 0; k2 < 2; k2++) {
                const __nv_bfloat16* Bq =
                    wqh + (q * 64 + wn * 32 + g) * 48 + 4 * tg + 16 * k2;
                uint2 bf[4];
#pragma unroll
                for (int nt = 0; nt < 4; nt++)
                    bf[nt] = *(const uint2*)(Bq + nt * 384);
                uint2 af[2][2];
#pragma unroll
                for (int mt = 0; mt < 2; mt++)
#pragma unroll
                    for (int r = 0; r < 2; r++)
                        af[mt][r] = *(const uint2*)(
                            hwc + (baseA[mt][r] + dq) * 40 + 4 * tg + 16 * k2);
#pragma unroll
                for (int mt = 0; mt < 2; mt++)
#pragma unroll
                    for (int nt = 0; nt < 4; nt++)
                        mma_bf16(acc[mt][nt], af[mt][0], af[mt][1], bf[nt]);
            }
        }

        // BN + ReLU -> feat[oc][pos] (separate f32 buffer; no hazard, no bar)
#pragma unroll
        for (int mt = 0; mt < 2; mt++) {
            const int m0 = wm * 32 + mt * 16 + g;
#pragma unroll
            for (int nt = 0; nt < 4; nt++) {
                const int c0 = wn * 32 + nt * 8 + 2 * tg;
                float s0 = sc2[c0], s1 = sc2[c0 + 1];
                float t0 = bi2[c0], t1 = bi2[c0 + 1];
                feat[c0 * 64 + m0]           = fmaxf(acc[mt][nt][0] * s0 + t0, 0.f);
                feat[(c0 + 1) * 64 + m0]     = fmaxf(acc[mt][nt][1] * s1 + t1, 0.f);
                feat[c0 * 64 + m0 + 8]       = fmaxf(acc[mt][nt][2] * s0 + t0, 0.f);
                feat[(c0 + 1) * 64 + m0 + 8] = fmaxf(acc[mt][nt][3] * s1 + t1, 0.f);
            }
        }
        BARG(grp);   // feat ready

        // Haar cD * upsample
        for (int qq = u; qq < 1024; qq += 128) {
            int c = qq >> 4, blk = qq & 15;
            int bI = blk >> 2, bJ = blk & 3;
            int p00 = c * 64 + (bI * 2) * 8 + bJ * 2;
            float a = feat[p00], b = feat[p00 + 1];
            float cc = feat[p00 + 8], d = feat[p00 + 9];
            float v = (a - b - cc + d) * 0.5f;
            feat[p00]     = a  * v;
            feat[p00 + 1] = b  * v;
            feat[p00 + 8] = cc * v;
            feat[p00 + 9] = d  * v;
        }
        BARG(grp);

        // 1x1 attn: two 32-channel partial sums per output
        {
            const int half = u >> 6, uu = u & 63;
            float s = (half == 0) ? bav : 0.f;
            const int cb = half * 32;
#pragma unroll 8
            for (int c = 0; c < 32; c++)
                s += feat[(cb + c) * 64 + uu] * was[cb + c];
            scr[half * 64 + uu] = s;
        }
        BARG(grp);
        if (u < 64) {
            float s = scr[u] + scr[64 + u];
            attn[u] = 1.f / (1.f + __expf(-s));
        }
        BARG(grp);

        // multiply & store bf16
        __nv_bfloat162* fg2 = (__nv_bfloat162*)(g_fh + (size_t)n * 4096);
        for (int i = 2 * u; i < 4096; i += 256) {
            float v0 = feat[i] * attn[i & 63];
            float v1 = feat[i + 1] * attn[(i + 1) & 63];
            fg2[i >> 1] = __floats2bfloat162_rn(v0, v1);
        }
        BARG(grp);   // feat/attn reads done
    }
}

// ============================================================================
// bf16 GEMM (PROVEN R13): 128x128, 256 thr, m16n8k16, 4-stage cp.async.
// MODE 0: g_h1h = bf16(relu(g_fh @ g_wd1h^T + bias))
// MODE 1: out   = sigmoid(g_h1h @ g_wd2h^T + bias)
// ============================================================================
#define GSTAGE 4
#define GSTRIDE_H 2048          // bf16 elems per stage: 128 rows * 16

template<int KDIM, int MODE>
__global__ __launch_bounds__(256, 2) void gemm_bf16_kernel(
    const float* __restrict__ bias, float* __restrict__ Cout)
{
    const __nv_bfloat16* A = (MODE == 0) ? g_fh  : g_h1h;
    const __nv_bfloat16* B = (MODE == 0) ? g_wd1h : g_wd2h;

    extern __shared__ __nv_bfloat16 smh[];
    __nv_bfloat16* As = smh;                          // [4][2048]
    __nv_bfloat16* Bs = smh + GSTAGE * GSTRIDE_H;     // [4][2048]
    const uint32_t AsU = (uint32_t)__cvta_generic_to_shared(As);
    const uint32_t BsU = (uint32_t)__cvta_generic_to_shared(Bs);

    const int t  = threadIdx.x;
    const int bn = blockIdx.x, bm = blockIdx.y;
    const int w  = t >> 5, lane = t & 31;
    const int wm = w >> 1, wn = w & 1;
    const int g  = lane >> 2, tg = lane & 3;

    const int lrow = t >> 1, lhalf = t & 1;
    const __nv_bfloat16* PA = A + (size_t)(bm * 128 + lrow) * KDIM + lhalf * 8;
    const __nv_bfloat16* PB = B + (size_t)(bn * 128 + lrow) * KDIM + lhalf * 8;
    const uint32_t DA = AsU + (lrow * 16 + lhalf * 8) * 2;
    const uint32_t DB = BsU + (lrow * 16 + lhalf * 8) * 2;

    const int NIT = KDIM / 16;

#pragma unroll
    for (int s = 0; s < 3; s++) {
        cp_async16(DA + s * (GSTRIDE_H * 2), PA + s * 16);
        cp_async16(DB + s * (GSTRIDE_H * 2), PB + s * 16);
        cp_commit();
    }

    float acc[2][8][4];
#pragma unroll
    for (int mt = 0; mt < 2; mt++)
#pragma unroll
        for (int nt = 0; nt < 8; nt++)
#pragma unroll
            for (int i = 0; i < 4; i++) acc[mt][nt][i] = 0.f;

    const int arow0 = (wm * 32 + g) * 16 + 4 * tg;
    const int brow0 = (wn * 64 + g) * 16 + 4 * tg;

#pragma unroll 1
    for (int it = 0; it < NIT; it++) {
        if (it < NIT - 2)       cp_wait<2>();
        else if (it == NIT - 2) cp_wait<1>();
        else                    cp_wait<0>();
        __syncthreads();

        if (it + 3 < NIT) {
            const int sn = (it + 3) & 3;
            cp_async16(DA + sn * (GSTRIDE_H * 2), PA + (it + 3) * 16);
            cp_async16(DB + sn * (GSTRIDE_H * 2), PB + (it + 3) * 16);
            cp_commit();
        }

        const int s = it & 3;
        const __nv_bfloat16* Ab = As + s * GSTRIDE_H;
        const __nv_bfloat16* Bb = Bs + s * GSTRIDE_H;

        uint2 afg[2], afg8[2], bf[8];
#pragma unroll
        for (int mt = 0; mt < 2; mt++) {
            afg[mt]  = *(const uint2*)(Ab + arow0 + mt * 256);
            afg8[mt] = *(const uint2*)(Ab + arow0 + mt * 256 + 128);
        }
#pragma unroll
        for (int nt = 0; nt < 8; nt++)
            bf[nt] = *(const uint2*)(Bb + brow0 + nt * 128);
#pragma unroll
        for (int mt = 0; mt < 2; mt++)
#pragma unroll
            for (int nt = 0; nt < 8; nt++)
                mma_bf16(acc[mt][nt], afg[mt], afg8[mt], bf[nt]);
    }

#pragma unroll
    for (int mt = 0; mt < 2; mt++) {
        const int m0 = bm * 128 + wm * 32 + mt * 16 + g;
#pragma unroll
        for (int nt = 0; nt < 8; nt++) {
            const int n0 = bn * 128 + wn * 64 + nt * 8 + 2 * tg;
            const float b0 = bias[n0], b1 = bias[n0 + 1];
            if (MODE == 0) {
                __nv_bfloat162 r0 = __floats2bfloat162_rn(
                    fmaxf(acc[mt][nt][0] + b0, 0.f), fmaxf(acc[mt][nt][1] + b1, 0.f));
                __nv_bfloat162 r1 = __floats2bfloat162_rn(
                    fmaxf(acc[mt][nt][2] + b0, 0.f), fmaxf(acc[mt][nt][3] + b1, 0.f));
                *(__nv_bfloat162*)&g_h1h[(size_t)m0 * 512 + n0]       = r0;
                *(__nv_bfloat162*)&g_h1h[(size_t)(m0 + 8) * 512 + n0] = r1;
            } else {
                float2 r0, r1;
                r0.x = 1.f / (1.f + __expf(-(acc[mt][nt][0] + b0)));
                r0.y = 1.f / (1.f + __expf(-(acc[mt][nt][1] + b1)));
                r1.x = 1.f / (1.f + __expf(-(acc[mt][nt][2] + b0)));
                r1.y = 1.f / (1.f + __expf(-(acc[mt][nt][3] + b1)));
                *(float2*)&Cout[(size_t)m0 * 128 + n0]       = r0;
                *(float2*)&Cout[(size_t)(m0 + 8) * 128 + n0] = r1;
            }
        }
    }
}

// ============================================================================
extern "C" void kernel_launch(void* const* d_in, const int* in_sizes, int n_in,
                              void* d_out, int out_size)
{
    const float* x   = (const float*)d_in[0];
    const float* w1  = (const float*)d_in[1];
    const float* b1  = (const float*)d_in[2];
    const float* g1  = (const float*)d_in[3];
    const float* be1 = (const float*)d_in[4];
    const float* m1  = (const float*)d_in[5];
    const float* v1  = (const float*)d_in[6];
    const float* w2  = (const float*)d_in[7];
    const float* b2  = (const float*)d_in[8];
    const float* g2  = (const float*)d_in[9];
    const float* be2 = (const float*)d_in[10];
    const float* m2  = (const float*)d_in[11];
    const float* v2  = (const float*)d_in[12];
    const float* wa  = (const float*)d_in[13];
    const float* ba  = (const float*)d_in[14];
    const float* wd1 = (const float*)d_in[15];
    const float* bd1 = (const float*)d_in[16];
    const float* wd2 = (const float*)d_in[17];
    const float* bd2 = (const float*)d_in[18];
    float* out = (float*)d_out;

    const int fused_smem = FU_BYTES;                        // 199,168 B
    const int gemm_smem  = GSTAGE * GSTRIDE_H * 2 * 2;      // 32,768 B
    cudaFuncSetAttribute(conv_fused_kernel,
                         cudaFuncAttributeMaxDynamicSharedMemorySize, fused_smem);
    cudaFuncSetAttribute(gemm_bf16_kernel<4096, 0>,
                         cudaFuncAttributeMaxDynamicSharedMemorySize, gemm_smem);
    cudaFuncSetAttribute(gemm_bf16_kernel<512, 1>,
                         cudaFuncAttributeMaxDynamicSharedMemorySize, gemm_smem);

    cvt_all_kernel<<<2204, 256>>>(wd1, wd2, w2, w1);

    conv_fused_kernel<<<148, 256, fused_smem>>>(x, b1, g1, be1, m1, v1,
                                                b2, g2, be2, m2, v2, wa, ba);

    dim3 grid_fc1(4, 64);
    gemm_bf16_kernel<4096, 0><<<grid_fc1, 256, gemm_smem>>>(bd1, out);
    dim3 grid_fc2(1, 64);
    gemm_bf16_kernel<512, 1><<<grid_fc2, 256, gemm_smem>>>(bd2, out);
}

// round 16
// speedup vs baseline: 1.8694x; 1.0075x over previous
#include <cuda_runtime.h>
#include <cuda_bf16.h>
#include <math.h>
#include <stdint.h>

#define BN_EPS 1e-5f
#define BATCH 8192

// ---------------- scratch (device globals; no allocations allowed) ----------
__device__ __nv_bfloat16 g_fh[(size_t)BATCH * 4096];   // flattened feat, bf16 (67MB)
__device__ __nv_bfloat16 g_h1h[(size_t)BATCH * 512];   // fc1 output, bf16 (8MB)
__device__ __nv_bfloat16 g_wd1h[(size_t)512 * 4096];   // bf16 wd1 (4MB)
__device__ __nv_bfloat16 g_wd2h[(size_t)128 * 512];    // bf16 wd2
__device__ __nv_bfloat16 g_wqh[(size_t)9 * 64 * 48];   // conv2 W [q][oc][ic pad48] bf16
__device__ __nv_bfloat16 g_w1h[(size_t)10 * 32 * 16];  // conv1 W [ky*2+h][oc][(px,ic4) 16] bf16

__device__ __forceinline__ void mma_bf16(float* c, uint2 arow_g, uint2 arow_g8, uint2 b)
{
    asm volatile(
        "mma.sync.aligned.m16n8k16.row.col.f32.bf16.bf16.f32 "
        "{%0,%1,%2,%3}, {%4,%5,%6,%7}, {%8,%9}, {%0,%1,%2,%3};\n"
        : "+f"(c[0]), "+f"(c[1]), "+f"(c[2]), "+f"(c[3])
        : "r"(arow_g.x), "r"(arow_g8.x), "r"(arow_g.y), "r"(arow_g8.y),
          "r"(b.x), "r"(b.y));
}

__device__ __forceinline__ void cp_async16(uint32_t dst_smem, const void* src) {
    asm volatile("cp.async.cg.shared.global [%0], [%1], 16;\n"
                 :: "r"(dst_smem), "l"(src));
}
__device__ __forceinline__ void cp_commit() {
    asm volatile("cp.async.commit_group;\n" ::: "memory");
}
template<int N>
__device__ __forceinline__ void cp_wait() {
    asm volatile("cp.async.wait_group %0;\n" :: "n"(N) : "memory");
}

#define BARG(grp) asm volatile("bar.sync %0, 128;" :: "r"((grp) + 1) : "memory")

__device__ __forceinline__ uint32_t smem_u32(const void* p) {
    return (uint32_t)__cvta_generic_to_shared(p);
}

// ============================================================================
// Merged prep: wd1->bf16 | wd2->bf16 | w2->wqh bf16 | w1->w1h bf16
// ============================================================================
__global__ __launch_bounds__(256) void cvt_all_kernel(
    const float* __restrict__ wd1, const float* __restrict__ wd2,
    const float* __restrict__ w2,  const float* __restrict__ w1)
{
    const int b = blockIdx.x, t = threadIdx.x;
    if (b < 2048) {
        int i = b * 256 + t;
        float4 v = ((const float4*)wd1)[i];
        ((__nv_bfloat162*)g_wd1h)[i * 2]     = __floats2bfloat162_rn(v.x, v.y);
        ((__nv_bfloat162*)g_wd1h)[i * 2 + 1] = __floats2bfloat162_rn(v.z, v.w);
    } else if (b < 2112) {
        int i = (b - 2048) * 256 + t;
        float4 v = ((const float4*)wd2)[i];
        ((__nv_bfloat162*)g_wd2h)[i * 2]     = __floats2bfloat162_rn(v.x, v.y);
        ((__nv_bfloat162*)g_wd2h)[i * 2 + 1] = __floats2bfloat162_rn(v.z, v.w);
    } else if (b < 2184) {
        int i = (b - 2112) * 256 + t;
        if (i < 18432) {
            int oc = i / 288;
            int rem = i % 288;
            int ic = rem / 9;
            int q  = rem % 9;
            g_wqh[(q * 64 + oc) * 48 + ic] = __float2bfloat16_rn(w2[i]);
        }
    } else {
        int i = (b - 2184) * 256 + t;
        if (i < 5120) {
            int j  = i & 15;
            int r  = i >> 4;
            int oc = r & 31;
            int kyh = r >> 5;
            int ky = kyh >> 1, h = kyh & 1;
            int p  = j >> 2, ic = j & 3;
            int kx = 4 * h + p;
            float v = (ic < 3 && kx < 5) ? w1[oc * 75 + ic * 25 + ky * 5 + kx] : 0.f;
            g_w1h[i] = __float2bfloat16_rn(v);
        }
    }
}

// ============================================================================
// FUSED conv1+conv2, all-bf16 (PROVEN R14, unchanged).
// ============================================================================
#define OF_WQH   0
#define OF_WBH   55296
#define OF_HWC   65536
#define OF_XS    117376
#define OF_STG   139264
#define OF_FEAT  163840
#define OF_ATTN  196608
#define OF_SCR   197120
#define OF_CON   198144
#define FU_BYTES 199168

__global__ __launch_bounds__(256) void conv_fused_kernel(
    const float* __restrict__ x,
    const float* __restrict__ b1, const float* __restrict__ g1,
    const float* __restrict__ be1, const float* __restrict__ m1,
    const float* __restrict__ v1,
    const float* __restrict__ b2, const float* __restrict__ g2,
    const float* __restrict__ be2, const float* __restrict__ m2,
    const float* __restrict__ v2, const float* __restrict__ wa,
    const float* __restrict__ ba)
{
    extern __shared__ char smc[];
    __nv_bfloat16* wqh = (__nv_bfloat16*)(smc + OF_WQH);
    __nv_bfloat16* wbh = (__nv_bfloat16*)(smc + OF_WBH);
    float* sc1 = (float*)(smc + OF_CON);
    float* bi1 = sc1 + 32;
    float* sc2 = bi1 + 32;
    float* bi2 = sc2 + 64;
    float* was = bi2 + 64;

    const int t = threadIdx.x;

    for (int i = t; i < 13824; i += 256) ((uint32_t*)wqh)[i] = ((const uint32_t*)g_wqh)[i];
    for (int i = t; i < 2560; i += 256)  ((uint32_t*)wbh)[i] = ((const uint32_t*)g_w1h)[i];
    for (int i = t; i < 12960; i += 256) ((uint32_t*)(smc + OF_HWC))[i] = 0;
    for (int i = t; i < 5472; i += 256)  ((uint32_t*)(smc + OF_XS))[i] = 0;
    if (t < 32) {
        float s = g1[t] * rsqrtf(v1[t] + BN_EPS);
        sc1[t] = s;
        bi1[t] = be1[t] + (b1[t] - m1[t]) * s;
    }
    if (t < 64) {
        float s = g2[t] * rsqrtf(v2[t] + BN_EPS);
        sc2[t] = s;
        bi2[t] = be2[t] + (b2[t] - m2[t]) * s;
        was[t] = wa[t];
    }
    const float bav = ba[0];
    __syncthreads();

    const int grp  = t >> 7;
    const int u    = t & 127;
    const int w4   = u >> 5;
    const int lane = u & 31;
    const int g    = lane >> 2, tg = lane & 3;
    const int wm   = w4 >> 1, wn = w4 & 1;

    __nv_bfloat16* hwc = (__nv_bfloat16*)(smc + OF_HWC) + grp * 12960;
    __nv_bfloat16* xs  = (__nv_bfloat16*)(smc + OF_XS)  + grp * 5472;
    float* stage = (float*)(smc + OF_STG)  + grp * 3072;
    float* feat  = (float*)(smc + OF_FEAT) + grp * 4096;
    float* attn  = (float*)(smc + OF_ATTN) + grp * 64;
    float* scr   = (float*)(smc + OF_SCR)  + grp * 128;
    const uint32_t stgU = smem_u32(stage);

    int baseA[2][2];
#pragma unroll
    for (int mt = 0; mt < 2; mt++)
#pragma unroll
        for (int r = 0; r < 2; r++) {
            int m = wm * 32 + mt * 16 + g + 8 * r;
            baseA[mt][r] = 36 * (m >> 3) + 2 * (m & 7);
        }

    const int stride = gridDim.x * 2;
    const int n0 = blockIdx.x * 2 + grp;

    if (n0 < BATCH) {
        const float* src = x + (size_t)n0 * 3072;
#pragma unroll
        for (int c = 0; c < 6; c++) {
            int idx = u + 128 * c;
            cp_async16(stgU + idx * 16, src + idx * 4);
        }
        cp_commit();
    }

    for (int n = n0; n < BATCH; n += stride) {
        cp_wait<0>();
#pragma unroll
        for (int j = 0; j < 8; j++) {
            int p = u + 128 * j;
            int iy = p >> 5, ix = p & 31;
            float f0 = stage[p];
            float f1 = stage[1024 + p];
            float f2 = stage[2048 + p];
            __nv_bfloat162 lo = __floats2bfloat162_rn(f0, f1);
            __nv_bfloat162 hi = __floats2bfloat162_rn(f2, 0.f);
            uint2 val = { *(uint32_t*)&lo, *(uint32_t*)&hi };
            *(uint2*)(xs + ((iy + 2) * 38 + ix + 2) * 4) = val;
        }
        BARG(grp);

        {
            float acc[4][4][4];
#pragma unroll
            for (int mt = 0; mt < 4; mt++)
#pragma unroll
                for (int nt = 0; nt < 4; nt++)
#pragma unroll
                    for (int i = 0; i < 4; i++) acc[mt][nt][i] = 0.f;

#pragma unroll
            for (int ky = 0; ky < 5; ky++) {
#pragma unroll
                for (int h = 0; h < 2; h++) {
                    const __nv_bfloat16* Bp = wbh + ((ky * 2 + h) * 32 + g) * 16 + 4 * tg;
                    uint2 bf[4];
#pragma unroll
                    for (int nt = 0; nt < 4; nt++)
                        bf[nt] = *(const uint2*)(Bp + nt * 128);
#pragma unroll
                    for (int mt = 0; mt < 4; mt++) {
                        const int oy = (w4 << 2) + mt;
                        const __nv_bfloat16* Ap =
                            xs + (2 * oy + ky) * 152 + (2 * g + 4 * h) * 4 + 4 * tg;
                        uint2 a0 = *(const uint2*)Ap;
                        uint2 a1 = *(const uint2*)(Ap + 64);
#pragma unroll
                        for (int nt = 0; nt < 4; nt++)
                            mma_bf16(acc[mt][nt], a0, a1, bf[nt]);
                    }
                }
            }

#pragma unroll
            for (int mt = 0; mt < 4; mt++) {
                const int oy = (w4 << 2) + mt;
#pragma unroll
                for (int nt = 0; nt < 4; nt++) {
                    const int oc = nt * 8 + 2 * tg;
                    const float s0 = sc1[oc], s1 = sc1[oc + 1];
                    const float t0 = bi1[oc], t1 = bi1[oc + 1];
                    __nv_bfloat162 r0 = __floats2bfloat162_rn(
                        fmaxf(acc[mt][nt][0] * s0 + t0, 0.f),
                        fmaxf(acc[mt][nt][1] * s1 + t1, 0.f));
                    __nv_bfloat162 r1 = __floats2bfloat162_rn(
                        fmaxf(acc[mt][nt][2] * s0 + t0, 0.f),
                        fmaxf(acc[mt][nt][3] * s1 + t1, 0.f));
                    const int p0 = (oy + 1) * 18 + g + 1;
                    *(__nv_bfloat162*)(hwc + p0 * 40 + oc)       = r0;
                    *(__nv_bfloat162*)(hwc + (p0 + 8) * 40 + oc) = r1;
                }
            }
            const int n_next = n + stride;
            if (n_next < BATCH) {
                const float* src = x + (size_t)n_next * 3072;
#pragma unroll
                for (int c = 0; c < 6; c++) {
                    int idx = u + 128 * c;
                    cp_async16(stgU + idx * 16, src + idx * 4);
                }
                cp_commit();
            }
        }
        BARG(grp);

        float acc[2][4][4];
#pragma unroll
        for (int mt = 0; mt < 2; mt++)
#pragma unroll
            for (int nt = 0; nt < 4; nt++)
#pragma unroll
                for (int i = 0; i < 4; i++) acc[mt][nt][i] = 0.f;

        for (int q = 0; q < 9; q++) {
            const int kh = q / 3, kw = q - kh * 3;
            const int dq = kh * 18 + kw;
#pragma unroll
            for (int k2 = 0; k2 < 2; k2++) {
                const __nv_bfloat16* Bq =
                    wqh + (q * 64 + wn * 32 + g) * 48 + 4 * tg + 16 * k2;
                uint2 bf[4];
#pragma unroll
                for (int nt = 0; nt < 4; nt++)
                    bf[nt] = *(const uint2*)(Bq + nt * 384);
                uint2 af[2][2];
#pragma unroll
                for (int mt = 0; mt < 2; mt++)
#pragma unroll
                    for (int r = 0; r < 2; r++)
                        af[mt][r] = *(const uint2*)(
                            hwc + (baseA[mt][r] + dq) * 40 + 4 * tg + 16 * k2);
#pragma unroll
                for (int mt = 0; mt < 2; mt++)
#pragma unroll
                    for (int nt = 0; nt < 4; nt++)
                        mma_bf16(acc[mt][nt], af[mt][0], af[mt][1], bf[nt]);
            }
        }

#pragma unroll
        for (int mt = 0; mt < 2; mt++) {
            const int m0 = wm * 32 + mt * 16 + g;
#pragma unroll
            for (int nt = 0; nt < 4; nt++) {
                const int c0 = wn * 32 + nt * 8 + 2 * tg;
                float s0 = sc2[c0], s1 = sc2[c0 + 1];
                float t0 = bi2[c0], t1 = bi2[c0 + 1];
                feat[c0 * 64 + m0]           = fmaxf(acc[mt][nt][0] * s0 + t0, 0.f);
                feat[(c0 + 1) * 64 + m0]     = fmaxf(acc[mt][nt][1] * s1 + t1, 0.f);
                feat[c0 * 64 + m0 + 8]       = fmaxf(acc[mt][nt][2] * s0 + t0, 0.f);
                feat[(c0 + 1) * 64 + m0 + 8] = fmaxf(acc[mt][nt][3] * s1 + t1, 0.f);
            }
        }
        BARG(grp);

        for (int qq = u; qq < 1024; qq += 128) {
            int c = qq >> 4, blk = qq & 15;
            int bI = blk >> 2, bJ = blk & 3;
            int p00 = c * 64 + (bI * 2) * 8 + bJ * 2;
            float a = feat[p00], b = feat[p00 + 1];
            float cc = feat[p00 + 8], d = feat[p00 + 9];
            float v = (a - b - cc + d) * 0.5f;
            feat[p00]     = a  * v;
            feat[p00 + 1] = b  * v;
            feat[p00 + 8] = cc * v;
            feat[p00 + 9] = d  * v;
        }
        BARG(grp);

        {
            const int half = u >> 6, uu = u & 63;
            float s = (half == 0) ? bav : 0.f;
            const int cb = half * 32;
#pragma unroll 8
            for (int c = 0; c < 32; c++)
                s += feat[(cb + c) * 64 + uu] * was[cb + c];
            scr[half * 64 + uu] = s;
        }
        BARG(grp);
        if (u < 64) {
            float s = scr[u] + scr[64 + u];
            attn[u] = 1.f / (1.f + __expf(-s));
        }
        BARG(grp);

        __nv_bfloat162* fg2 = (__nv_bfloat162*)(g_fh + (size_t)n * 4096);
        for (int i = 2 * u; i < 4096; i += 256) {
            float v0 = feat[i] * attn[i & 63];
            float v1 = feat[i + 1] * attn[(i + 1) & 63];
            fg2[i >> 1] = __floats2bfloat162_rn(v0, v1);
        }
        BARG(grp);
    }
}

// ============================================================================
// fc1: bf16 GEMM 128x256 tile, 256 threads (8 warps, warp tile 32x128),
// m16n8k16, cp.async 4-stage, distance-3 prefetch, one barrier per k16.
// Derived isomorphically from the PROVEN R13 gemm; N widened 128->256:
//   nt 8->16, wn spans 128 cols, B smem 256 rows (per-thread: 1 A + 2 B chunks).
// g_h1h = bf16(relu(g_fh @ g_wd1h^T + bias))
// ============================================================================
#define F1_AS 2048              // A elems per stage (128 rows * 16)
#define F1_BS 4096              // B elems per stage (256 rows * 16)
#define F1_SMEM (4 * (F1_AS + F1_BS) * 2)

__global__ __launch_bounds__(256, 1) void fc1_wide_kernel(const float* __restrict__ bias)
{
    extern __shared__ __nv_bfloat16 smh[];
    __nv_bfloat16* As = smh;                 // [4][2048]
    __nv_bfloat16* Bs = smh + 4 * F1_AS;     // [4][4096]
    const uint32_t AsU = smem_u32(As);
    const uint32_t BsU = smem_u32(Bs);

    const int t  = threadIdx.x;
    const int bn = blockIdx.x, bm = blockIdx.y;     // (2, 64)
    const int w  = t >> 5, lane = t & 31;
    const int wm = w >> 1, wn = w & 1;              // 4 x 2 warps; warp tile 32x128
    const int g  = lane >> 2, tg = lane & 3;

    // loaders: A chunk j=t (128 rows x 2 halves); B chunks j=t, t+256 (256 rows x 2)
    const int arow = t >> 1, ahalf = t & 1;
    const __nv_bfloat16* PA = g_fh + (size_t)(bm * 128 + arow) * 4096 + ahalf * 8;
    const uint32_t DA = AsU + (arow * 16 + ahalf * 8) * 2;
    const __nv_bfloat16* PB[2];
    uint32_t DB[2];
#pragma unroll
    for (int e = 0; e < 2; e++) {
        int je = t + 256 * e;
        int brow = je >> 1, bhalf = je & 1;
        PB[e] = g_wd1h + (size_t)(bn * 256 + brow) * 4096 + bhalf * 8;
        DB[e] = BsU + (brow * 16 + bhalf * 8) * 2;
    }

    const int NIT = 256;    // K = 4096 / 16

#pragma unroll
    for (int s = 0; s < 3; s++) {
        cp_async16(DA + s * (F1_AS * 2), PA + s * 16);
        cp_async16(DB[0] + s * (F1_BS * 2), PB[0] + s * 16);
        cp_async16(DB[1] + s * (F1_BS * 2), PB[1] + s * 16);
        cp_commit();
    }

    float acc[2][16][4];
#pragma unroll
    for (int mt = 0; mt < 2; mt++)
#pragma unroll
        for (int nt = 0; nt < 16; nt++)
#pragma unroll
            for (int i = 0; i < 4; i++) acc[mt][nt][i] = 0.f;

    const int arow0 = (wm * 32 + g) * 16 + 4 * tg;      // +mt*256, +128 row+8
    const int brow0 = (wn * 128 + g) * 16 + 4 * tg;     // +nt*128

#pragma unroll 1
    for (int it = 0; it < NIT; it++) {
        if (it < NIT - 2)       cp_wait<2>();
        else if (it == NIT - 2) cp_wait<1>();
        else                    cp_wait<0>();
        __syncthreads();

        if (it + 3 < NIT) {
            const int sn = (it + 3) & 3;
            cp_async16(DA + sn * (F1_AS * 2), PA + (it + 3) * 16);
            cp_async16(DB[0] + sn * (F1_BS * 2), PB[0] + (it + 3) * 16);
            cp_async16(DB[1] + sn * (F1_BS * 2), PB[1] + (it + 3) * 16);
            cp_commit();
        }

        const int s = it & 3;
        const __nv_bfloat16* Ab = As + s * F1_AS;
        const __nv_bfloat16* Bb = Bs + s * F1_BS;

        uint2 afg[2], afg8[2];
#pragma unroll
        for (int mt = 0; mt < 2; mt++) {
            afg[mt]  = *(const uint2*)(Ab + arow0 + mt * 256);
            afg8[mt] = *(const uint2*)(Ab + arow0 + mt * 256 + 128);
        }
#pragma unroll
        for (int nt = 0; nt < 16; nt++) {
            uint2 bf = *(const uint2*)(Bb + brow0 + nt * 128);
#pragma unroll
            for (int mt = 0; mt < 2; mt++)
                mma_bf16(acc[mt][nt], afg[mt], afg8[mt], bf);
        }
    }

#pragma unroll
    for (int mt = 0; mt < 2; mt++) {
        const int m0 = bm * 128 + wm * 32 + mt * 16 + g;
#pragma unroll
        for (int nt = 0; nt < 16; nt++) {
            const int n0 = bn * 256 + wn * 128 + nt * 8 + 2 * tg;
            const float b0 = bias[n0], b1 = bias[n0 + 1];
            __nv_bfloat162 r0 = __floats2bfloat162_rn(
                fmaxf(acc[mt][nt][0] + b0, 0.f), fmaxf(acc[mt][nt][1] + b1, 0.f));
            __nv_bfloat162 r1 = __floats2bfloat162_rn(
                fmaxf(acc[mt][nt][2] + b0, 0.f), fmaxf(acc[mt][nt][3] + b1, 0.f));
            *(__nv_bfloat162*)&g_h1h[(size_t)m0 * 512 + n0]       = r0;
            *(__nv_bfloat162*)&g_h1h[(size_t)(m0 + 8) * 512 + n0] = r1;
        }
    }
}

// ============================================================================
// bf16 GEMM (PROVEN R13) — fc2 only.
// MODE 1: out = sigmoid(g_h1h @ g_wd2h^T + bias)
// ============================================================================
#define GSTAGE 4
#define GSTRIDE_H 2048

template<int KDIM, int MODE>
__global__ __launch_bounds__(256, 2) void gemm_bf16_kernel(
    const float* __restrict__ bias, float* __restrict__ Cout)
{
    const __nv_bfloat16* A = (MODE == 0) ? g_fh  : g_h1h;
    const __nv_bfloat16* B = (MODE == 0) ? g_wd1h : g_wd2h;

    extern __shared__ __nv_bfloat16 smh2[];
    __nv_bfloat16* As = smh2;
    __nv_bfloat16* Bs = smh2 + GSTAGE * GSTRIDE_H;
    const uint32_t AsU = smem_u32(As);
    const uint32_t BsU = smem_u32(Bs);

    const int t  = threadIdx.x;
    const int bn = blockIdx.x, bm = blockIdx.y;
    const int w  = t >> 5, lane = t & 31;
    const int wm = w >> 1, wn = w & 1;
    const int g  = lane >> 2, tg = lane & 3;

    const int lrow = t >> 1, lhalf = t & 1;
    const __nv_bfloat16* PA = A + (size_t)(bm * 128 + lrow) * KDIM + lhalf * 8;
    const __nv_bfloat16* PB = B + (size_t)(bn * 128 + lrow) * KDIM + lhalf * 8;
    const uint32_t DA = AsU + (lrow * 16 + lhalf * 8) * 2;
    const uint32_t DB = BsU + (lrow * 16 + lhalf * 8) * 2;

    const int NIT = KDIM / 16;

#pragma unroll
    for (int s = 0; s < 3; s++) {
        cp_async16(DA + s * (GSTRIDE_H * 2), PA + s * 16);
        cp_async16(DB + s * (GSTRIDE_H * 2), PB + s * 16);
        cp_commit();
    }

    float acc[2][8][4];
#pragma unroll
    for (int mt = 0; mt < 2; mt++)
#pragma unroll
        for (int nt = 0; nt < 8; nt++)
#pragma unroll
            for (int i = 0; i < 4; i++) acc[mt][nt][i] = 0.f;

    const int arow0 = (wm * 32 + g) * 16 + 4 * tg;
    const int brow0 = (wn * 64 + g) * 16 + 4 * tg;

#pragma unroll 1
    for (int it = 0; it < NIT; it++) {
        if (it < NIT - 2)       cp_wait<2>();
        else if (it == NIT - 2) cp_wait<1>();
        else                    cp_wait<0>();
        __syncthreads();

        if (it + 3 < NIT) {
            const int sn = (it + 3) & 3;
            cp_async16(DA + sn * (GSTRIDE_H * 2), PA + (it + 3) * 16);
            cp_async16(DB + sn * (GSTRIDE_H * 2), PB + (it + 3) * 16);
            cp_commit();
        }

        const int s = it & 3;
        const __nv_bfloat16* Ab = As + s * GSTRIDE_H;
        const __nv_bfloat16* Bb = Bs + s * GSTRIDE_H;

        uint2 afg[2], afg8[2], bf[8];
#pragma unroll
        for (int mt = 0; mt < 2; mt++) {
            afg[mt]  = *(const uint2*)(Ab + arow0 + mt * 256);
            afg8[mt] = *(const uint2*)(Ab + arow0 + mt * 256 + 128);
        }
#pragma unroll
        for (int nt = 0; nt < 8; nt++)
            bf[nt] = *(const uint2*)(Bb + brow0 + nt * 128);
#pragma unroll
        for (int mt = 0; mt < 2; mt++)
#pragma unroll
            for (int nt = 0; nt < 8; nt++)
                mma_bf16(acc[mt][nt], afg[mt], afg8[mt], bf[nt]);
    }

#pragma unroll
    for (int mt = 0; mt < 2; mt++) {
        const int m0 = bm * 128 + wm * 32 + mt * 16 + g;
#pragma unroll
        for (int nt = 0; nt < 8; nt++) {
            const int n0 = bn * 128 + wn * 64 + nt * 8 + 2 * tg;
            const float b0 = bias[n0], b1 = bias[n0 + 1];
            if (MODE == 0) {
                __nv_bfloat162 r0 = __floats2bfloat162_rn(
                    fmaxf(acc[mt][nt][0] + b0, 0.f), fmaxf(acc[mt][nt][1] + b1, 0.f));
                __nv_bfloat162 r1 = __floats2bfloat162_rn(
                    fmaxf(acc[mt][nt][2] + b0, 0.f), fmaxf(acc[mt][nt][3] + b1, 0.f));
                *(__nv_bfloat162*)&g_h1h[(size_t)m0 * 512 + n0]       = r0;
                *(__nv_bfloat162*)&g_h1h[(size_t)(m0 + 8) * 512 + n0] = r1;
            } else {
                float2 r0, r1;
                r0.x = 1.f / (1.f + __expf(-(acc[mt][nt][0] + b0)));
                r0.y = 1.f / (1.f + __expf(-(acc[mt][nt][1] + b1)));
                r1.x = 1.f / (1.f + __expf(-(acc[mt][nt][2] + b0)));
                r1.y = 1.f / (1.f + __expf(-(acc[mt][nt][3] + b1)));
                *(float2*)&Cout[(size_t)m0 * 128 + n0]       = r0;
                *(float2*)&Cout[(size_t)(m0 + 8) * 128 + n0] = r1;
            }
        }
    }
}

// ============================================================================
extern "C" void kernel_launch(void* const* d_in, const int* in_sizes, int n_in,
                              void* d_out, int out_size)
{
    const float* x   = (const float*)d_in[0];
    const float* w1  = (const float*)d_in[1];
    const float* b1  = (const float*)d_in[2];
    const float* g1  = (const float*)d_in[3];
    const float* be1 = (const float*)d_in[4];
    const float* m1  = (const float*)d_in[5];
    const float* v1  = (const float*)d_in[6];
    const float* w2  = (const float*)d_in[7];
    const float* b2  = (const float*)d_in[8];
    const float* g2  = (const float*)d_in[9];
    const float* be2 = (const float*)d_in[10];
    const float* m2  = (const float*)d_in[11];
    const float* v2  = (const float*)d_in[12];
    const float* wa  = (const float*)d_in[13];
    const float* ba  = (const float*)d_in[14];
    const float* wd1 = (const float*)d_in[15];
    const float* bd1 = (const float*)d_in[16];
    const float* wd2 = (const float*)d_in[17];
    const float* bd2 = (const float*)d_in[18];
    float* out = (float*)d_out;

    const int gemm_smem = GSTAGE * GSTRIDE_H * 2 * 2;
    cudaFuncSetAttribute(conv_fused_kernel,
                         cudaFuncAttributeMaxDynamicSharedMemorySize, FU_BYTES);
    cudaFuncSetAttribute(fc1_wide_kernel,
                         cudaFuncAttributeMaxDynamicSharedMemorySize, F1_SMEM);
    cudaFuncSetAttribute(gemm_bf16_kernel<512, 1>,
                         cudaFuncAttributeMaxDynamicSharedMemorySize, gemm_smem);

    cvt_all_kernel<<<2204, 256>>>(wd1, wd2, w2, w1);

    conv_fused_kernel<<<148, 256, FU_BYTES>>>(x, b1, g1, be1, m1, v1,
                                              b2, g2, be2, m2, v2, wa, ba);

    dim3 grid_fc1(2, 64);
    fc1_wide_kernel<<<grid_fc1, 256, F1_SMEM>>>(bd1);
    dim3 grid_fc2(1, 64);
    gemm_bf16_kernel<512, 1><<<grid_fc2, 256, gemm_smem>>>(bd2, out);
}